// round 1
// baseline (speedup 1.0000x reference)
#include <cuda_runtime.h>
#include <cstdint>

// ---------------------------------------------------------------------------
// Problem constants
// ---------------------------------------------------------------------------
#define BATCH 1024
#define NTOK  64
#define CDIM  512
#define NHEAD 8
#define HDIM  64
#define NWIN  64          // windows per image (mask group)
#define MTOT  (BATCH * NTOK)      // 65536
#define QKVN  (3 * CDIM)          // 1536

// scratch (device globals: allocation-free)
__device__ float g_qkv[100663296];   // [1024][64][1536]
__device__ float g_att[33554432];    // [1024][64][512]
__device__ float g_cpb[225 * 8];     // cpb table [t][h]

// ---------------------------------------------------------------------------
// f32x2 packed math helpers (B300: FFMA2 gives 2x fp32 FMA throughput)
// ---------------------------------------------------------------------------
__device__ __forceinline__ unsigned long long pack2(float x, float y) {
    unsigned long long r;
    asm("mov.b64 %0, {%1, %2};" : "=l"(r) : "r"(__float_as_uint(x)), "r"(__float_as_uint(y)));
    return r;
}
__device__ __forceinline__ void fma2(unsigned long long& d, unsigned long long a, unsigned long long b) {
    asm("fma.rn.f32x2 %0, %1, %2, %0;" : "+l"(d) : "l"(a), "l"(b));
}
__device__ __forceinline__ void unpack2(unsigned long long v, float& x, float& y) {
    unsigned int lo, hi;
    asm("mov.b64 {%0, %1}, %2;" : "=r"(lo), "=r"(hi) : "l"(v));
    x = __uint_as_float(lo); y = __uint_as_float(hi);
}

// ---------------------------------------------------------------------------
// Kernel 1: continuous relative position bias MLP -> g_cpb[225][8]
// ---------------------------------------------------------------------------
__device__ __forceinline__ float signed_log_coord(int d) {
    float g = (float)d / 7.0f * 8.0f;
    float s = (g > 0.f) ? 1.f : ((g < 0.f) ? -1.f : 0.f);
    return s * log2f(fabsf(g) + 1.0f) / log2f(9.0f);
}

__global__ void cpb_kernel(const float* __restrict__ w1, const float* __restrict__ b1,
                           const float* __restrict__ w2) {
    int t = blockIdx.x;                // 0..224
    int dh = t / 15 - 7;
    int dw = t % 15 - 7;
    float c0 = signed_log_coord(dh);
    float c1 = signed_log_coord(dw);

    __shared__ float red[64][8];
    float p[8];
#pragma unroll
    for (int h = 0; h < 8; h++) p[h] = 0.f;

    for (int j = threadIdx.x; j < 512; j += 64) {
        float hx = fmaf(c0, w1[2 * j], fmaf(c1, w1[2 * j + 1], b1[j]));
        hx = fmaxf(hx, 0.f);
#pragma unroll
        for (int h = 0; h < 8; h++) p[h] += hx * w2[h * 512 + j];
    }
#pragma unroll
    for (int h = 0; h < 8; h++) red[threadIdx.x][h] = p[h];
    __syncthreads();
    if (threadIdx.x < 8) {
        float s = 0.f;
#pragma unroll
        for (int i = 0; i < 64; i++) s += red[i][threadIdx.x];
        float sig = 1.f / (1.f + expf(-s));
        g_cpb[t * 8 + threadIdx.x] = 16.f * sig;
    }
}

// ---------------------------------------------------------------------------
// Kernel 2/4: SGEMM-NT  C[m][n] = sum_k A[m][k]*B[n][k] + bias(n)
// A: MxK row-major, B: NxK row-major.  BM=BN=128, BK=16, 256 threads, 8x8/thr.
// bias_mode 0: n<512 -> bq[n]; 512<=n<1024 -> 0; n>=1024 -> bv[n-1024]
// bias_mode 1: bq[n]
// ---------------------------------------------------------------------------
#define BM 128
#define BN 128
#define BK 16

__global__ void __launch_bounds__(256, 2)
sgemm_nt(const float* __restrict__ A, const float* __restrict__ Bw,
         float* __restrict__ C, int M, int N, int K,
         const float* __restrict__ bq, const float* __restrict__ bv, int bias_mode) {
    __shared__ float As[BK * BM];
    __shared__ float Bs[BK * BN];

    const int tid = threadIdx.x;
    const int row0 = blockIdx.y * BM;
    const int col0 = blockIdx.x * BN;

    const int lr = tid >> 2;          // 0..63
    const int lc = (tid & 3) * 4;     // k offset 0,4,8,12

    const int tx = tid & 15;          // n dir
    const int ty = tid >> 4;          // m dir

    unsigned long long acc[8][4];
#pragma unroll
    for (int i = 0; i < 8; i++)
#pragma unroll
        for (int j = 0; j < 4; j++) acc[i][j] = 0ull;

    const float* Ap0 = A + (size_t)(row0 + lr) * K + lc;
    const float* Ap1 = A + (size_t)(row0 + lr + 64) * K + lc;
    const float* Bp0 = Bw + (size_t)(col0 + lr) * K + lc;
    const float* Bp1 = Bw + (size_t)(col0 + lr + 64) * K + lc;

    for (int kt = 0; kt < K; kt += BK) {
        float4 a0 = *(const float4*)(Ap0 + kt);
        float4 a1 = *(const float4*)(Ap1 + kt);
        float4 b0 = *(const float4*)(Bp0 + kt);
        float4 b1 = *(const float4*)(Bp1 + kt);
        __syncthreads();
        As[(lc + 0) * BM + lr] = a0.x;  As[(lc + 1) * BM + lr] = a0.y;
        As[(lc + 2) * BM + lr] = a0.z;  As[(lc + 3) * BM + lr] = a0.w;
        As[(lc + 0) * BM + lr + 64] = a1.x;  As[(lc + 1) * BM + lr + 64] = a1.y;
        As[(lc + 2) * BM + lr + 64] = a1.z;  As[(lc + 3) * BM + lr + 64] = a1.w;
        Bs[(lc + 0) * BN + lr] = b0.x;  Bs[(lc + 1) * BN + lr] = b0.y;
        Bs[(lc + 2) * BN + lr] = b0.z;  Bs[(lc + 3) * BN + lr] = b0.w;
        Bs[(lc + 0) * BN + lr + 64] = b1.x;  Bs[(lc + 1) * BN + lr + 64] = b1.y;
        Bs[(lc + 2) * BN + lr + 64] = b1.z;  Bs[(lc + 3) * BN + lr + 64] = b1.w;
        __syncthreads();

#pragma unroll
        for (int kk = 0; kk < BK; kk++) {
            float4 av0 = *(const float4*)(As + kk * BM + ty * 8);
            float4 av1 = *(const float4*)(As + kk * BM + ty * 8 + 4);
            float4 bv0 = *(const float4*)(Bs + kk * BN + tx * 8);
            float4 bv1 = *(const float4*)(Bs + kk * BN + tx * 8 + 4);
            unsigned long long bp[4];
            bp[0] = pack2(bv0.x, bv0.y);
            bp[1] = pack2(bv0.z, bv0.w);
            bp[2] = pack2(bv1.x, bv1.y);
            bp[3] = pack2(bv1.z, bv1.w);
            float am[8] = {av0.x, av0.y, av0.z, av0.w, av1.x, av1.y, av1.z, av1.w};
#pragma unroll
            for (int i = 0; i < 8; i++) {
                unsigned long long aa = pack2(am[i], am[i]);
                fma2(acc[i][0], aa, bp[0]);
                fma2(acc[i][1], aa, bp[1]);
                fma2(acc[i][2], aa, bp[2]);
                fma2(acc[i][3], aa, bp[3]);
            }
        }
    }

    // epilogue
#pragma unroll
    for (int i = 0; i < 8; i++) {
        int m = row0 + ty * 8 + i;
        float o[8];
        unpack2(acc[i][0], o[0], o[1]);
        unpack2(acc[i][1], o[2], o[3]);
        unpack2(acc[i][2], o[4], o[5]);
        unpack2(acc[i][3], o[6], o[7]);
#pragma unroll
        for (int j = 0; j < 8; j++) {
            int n = col0 + tx * 8 + j;
            float bias;
            if (bias_mode == 0) {
                bias = (n < 512) ? bq[n] : ((n < 1024) ? 0.f : bv[n - 1024]);
            } else {
                bias = bq[n];
            }
            o[j] += bias;
        }
        float4* dst = (float4*)(C + (size_t)m * N + col0 + tx * 8);
        dst[0] = make_float4(o[0], o[1], o[2], o[3]);
        dst[1] = make_float4(o[4], o[5], o[6], o[7]);
    }
}

// ---------------------------------------------------------------------------
// Kernel 3: fused per-(b,h) attention. grid = (1024, 8), 256 threads.
// smem: sq,sk,sv,ss each [64][65] + cpb[225]   (dynamic, ~67.5 KB)
// ---------------------------------------------------------------------------
__global__ void __launch_bounds__(256)
attn_kernel(const float* __restrict__ qkv, const float* __restrict__ mask,
            const float* __restrict__ logit_scale, float* __restrict__ attout) {
    const int b = blockIdx.x;
    const int h = blockIdx.y;
    extern __shared__ float sm[];
    float* sq = sm;              // [64][65]
    float* sk = sm + 4160;
    float* sv = sm + 8320;
    float* ss = sm + 12480;
    float* scpb = sm + 16640;    // [225]

    const int tid = threadIdx.x;
    if (tid < 225) scpb[tid] = g_cpb[tid * 8 + h];

    const float* base = qkv + (size_t)b * NTOK * QKVN + h * HDIM;
#pragma unroll
    for (int it = 0; it < 4; it++) {
        int f = tid + it * 256;          // float4 index 0..1023
        int n = f >> 4;
        int d4 = (f & 15) << 2;
        const float* rp = base + (size_t)n * QKVN + d4;
        float4 q4 = *(const float4*)(rp);
        float4 k4 = *(const float4*)(rp + CDIM);
        float4 v4 = *(const float4*)(rp + 2 * CDIM);
        float* qd = sq + n * 65 + d4;
        float* kd = sk + n * 65 + d4;
        float* vd = sv + n * 65 + d4;
        qd[0] = q4.x; qd[1] = q4.y; qd[2] = q4.z; qd[3] = q4.w;
        kd[0] = k4.x; kd[1] = k4.y; kd[2] = k4.z; kd[3] = k4.w;
        vd[0] = v4.x; vd[1] = v4.y; vd[2] = v4.z; vd[3] = v4.w;
    }
    __syncthreads();

    // row-normalize q and k (warp per 8 rows)
    const int warp = tid >> 5, lane = tid & 31;
#pragma unroll
    for (int rr = 0; rr < 8; rr++) {
        int row = warp * 8 + rr;
        // q
        {
            float x0 = sq[row * 65 + lane], x1 = sq[row * 65 + lane + 32];
            float s = x0 * x0 + x1 * x1;
#pragma unroll
            for (int o = 16; o; o >>= 1) s += __shfl_xor_sync(0xffffffffu, s, o);
            float inv = 1.f / fmaxf(sqrtf(s), 1e-12f);
            sq[row * 65 + lane] = x0 * inv;
            sq[row * 65 + lane + 32] = x1 * inv;
        }
        // k
        {
            float x0 = sk[row * 65 + lane], x1 = sk[row * 65 + lane + 32];
            float s = x0 * x0 + x1 * x1;
#pragma unroll
            for (int o = 16; o; o >>= 1) s += __shfl_xor_sync(0xffffffffu, s, o);
            float inv = 1.f / fmaxf(sqrtf(s), 1e-12f);
            sk[row * 65 + lane] = x0 * inv;
            sk[row * 65 + lane + 32] = x1 * inv;
        }
    }
    __syncthreads();

    const float scale = expf(fminf(logit_scale[h], 4.60517018598809f));  // ln(100)

    const int tx = tid & 15, ty = tid >> 4;
    const int j0 = tx * 4, i0 = ty * 4;

    // S = q_n @ k_n^T
    float acc[4][4];
#pragma unroll
    for (int i = 0; i < 4; i++)
#pragma unroll
        for (int j = 0; j < 4; j++) acc[i][j] = 0.f;

    for (int kk = 0; kk < 64; kk++) {
        float a[4], bb[4];
#pragma unroll
        for (int i = 0; i < 4; i++) a[i] = sq[(i0 + i) * 65 + kk];
#pragma unroll
        for (int j = 0; j < 4; j++) bb[j] = sk[(j0 + j) * 65 + kk];
#pragma unroll
        for (int i = 0; i < 4; i++)
#pragma unroll
            for (int j = 0; j < 4; j++) acc[i][j] = fmaf(a[i], bb[j], acc[i][j]);
    }

    const int w = b & (NWIN - 1);
    const float* mrow = mask + (size_t)w * NTOK * NTOK;
#pragma unroll
    for (int i = 0; i < 4; i++) {
        int I = i0 + i;
#pragma unroll
        for (int j = 0; j < 4; j++) {
            int J = j0 + j;
            int t = ((I >> 3) - (J >> 3) + 7) * 15 + ((I & 7) - (J & 7) + 7);
            ss[I * 65 + J] = fmaf(acc[i][j], scale, scpb[t]) + __ldg(mrow + I * 64 + J);
        }
    }
    __syncthreads();

    // softmax per row
#pragma unroll
    for (int rr = 0; rr < 8; rr++) {
        int row = warp * 8 + rr;
        float x0 = ss[row * 65 + lane], x1 = ss[row * 65 + lane + 32];
        float m = fmaxf(x0, x1);
#pragma unroll
        for (int o = 16; o; o >>= 1) m = fmaxf(m, __shfl_xor_sync(0xffffffffu, m, o));
        float e0 = expf(x0 - m), e1 = expf(x1 - m);
        float s = e0 + e1;
#pragma unroll
        for (int o = 16; o; o >>= 1) s += __shfl_xor_sync(0xffffffffu, s, o);
        float inv = 1.f / s;
        ss[row * 65 + lane] = e0 * inv;
        ss[row * 65 + lane + 32] = e1 * inv;
    }
    __syncthreads();

    // O = P @ V
    float oacc[4][4];
#pragma unroll
    for (int i = 0; i < 4; i++)
#pragma unroll
        for (int d = 0; d < 4; d++) oacc[i][d] = 0.f;

    for (int j = 0; j < 64; j++) {
        float p[4], vv[4];
#pragma unroll
        for (int i = 0; i < 4; i++) p[i] = ss[(i0 + i) * 65 + j];
#pragma unroll
        for (int d = 0; d < 4; d++) vv[d] = sv[j * 65 + j0 + d];
#pragma unroll
        for (int i = 0; i < 4; i++)
#pragma unroll
            for (int d = 0; d < 4; d++) oacc[i][d] = fmaf(p[i], vv[d], oacc[i][d]);
    }

    float* ob = attout + (size_t)b * NTOK * CDIM + h * HDIM;
#pragma unroll
    for (int i = 0; i < 4; i++) {
        float4 v4 = make_float4(oacc[i][0], oacc[i][1], oacc[i][2], oacc[i][3]);
        *(float4*)(ob + (size_t)(i0 + i) * CDIM + j0) = v4;
    }
}

// ---------------------------------------------------------------------------
// launch
// ---------------------------------------------------------------------------
extern "C" void kernel_launch(void* const* d_in, const int* in_sizes, int n_in,
                              void* d_out, int out_size) {
    const float* x           = (const float*)d_in[0];
    const float* mask        = (const float*)d_in[1];
    const float* qkv_w       = (const float*)d_in[2];
    const float* q_bias      = (const float*)d_in[3];
    const float* v_bias      = (const float*)d_in[4];
    const float* logit_scale = (const float*)d_in[5];
    const float* cpb_w1      = (const float*)d_in[6];
    const float* cpb_b1      = (const float*)d_in[7];
    const float* cpb_w2      = (const float*)d_in[8];
    const float* proj_w      = (const float*)d_in[9];
    const float* proj_b      = (const float*)d_in[10];
    float* out = (float*)d_out;

    float* qkv_ptr = nullptr;
    float* att_ptr = nullptr;
    cudaGetSymbolAddress((void**)&qkv_ptr, g_qkv);
    cudaGetSymbolAddress((void**)&att_ptr, g_att);

    // 1. cpb table
    cpb_kernel<<<225, 64>>>(cpb_w1, cpb_b1, cpb_w2);

    // 2. QKV projection: [65536,512] x [1536,512]^T
    {
        dim3 grid(QKVN / BN, MTOT / BM);
        sgemm_nt<<<grid, 256>>>(x, qkv_w, qkv_ptr, MTOT, QKVN, CDIM,
                                q_bias, v_bias, 0);
    }

    // 3. fused attention
    {
        size_t smem = (4 * 4160 + 256) * sizeof(float);  // 67.6 KB
        cudaFuncSetAttribute(attn_kernel, cudaFuncAttributeMaxDynamicSharedMemorySize,
                             (int)smem);
        dim3 grid(BATCH, NHEAD);
        attn_kernel<<<grid, 256, smem>>>(qkv_ptr, mask, logit_scale, att_ptr);
    }

    // 4. output projection: [65536,512] x [512,512]^T
    {
        dim3 grid(CDIM / BN, MTOT / BM);
        sgemm_nt<<<grid, 256>>>(att_ptr, proj_w, out, MTOT, CDIM, CDIM,
                                proj_b, nullptr, 1);
    }
}

// round 3
// speedup vs baseline: 3.3829x; 3.3829x over previous
#include <cuda_runtime.h>
#include <cuda_bf16.h>
#include <cstdint>

// ---------------------------------------------------------------------------
// Problem constants
// ---------------------------------------------------------------------------
#define BATCH 1024
#define NTOK  64
#define CDIM  512
#define NHEAD 8
#define HDIM  64
#define MTOT  (BATCH * NTOK)      // 65536
#define QKVN  (3 * CDIM)          // 1536

// ---------------------------------------------------------------------------
// Device-global scratch (allocation-free)
// ---------------------------------------------------------------------------
__device__ __align__(16) float          g_qkv[(size_t)MTOT * QKVN];
__device__ __align__(16) __nv_bfloat16  g_xhi[(size_t)MTOT * CDIM];
__device__ __align__(16) __nv_bfloat16  g_xlo[(size_t)MTOT * CDIM];
__device__ __align__(16) __nv_bfloat16  g_whi[QKVN * CDIM];
__device__ __align__(16) __nv_bfloat16  g_wlo[QKVN * CDIM];
__device__ __align__(16) __nv_bfloat16  g_phi[CDIM * CDIM];
__device__ __align__(16) __nv_bfloat16  g_plo[CDIM * CDIM];
__device__ __align__(16) __nv_bfloat16  g_ahi[(size_t)MTOT * CDIM];
__device__ __align__(16) __nv_bfloat16  g_alo[(size_t)MTOT * CDIM];
__device__ __align__(16) float          g_bias[QKVN];
__device__ __align__(16) float          g_cpb[225 * 8];

// ---------------------------------------------------------------------------
// PTX helpers (baseline ISA only: cp.async, ldmatrix, mma.sync)
// ---------------------------------------------------------------------------
__device__ __forceinline__ uint32_t s2u(const void* p) {
    return (uint32_t)__cvta_generic_to_shared(p);
}
__device__ __forceinline__ void cpa16(uint32_t saddr, const void* g) {
    asm volatile("cp.async.cg.shared.global [%0], [%1], 16;" :: "r"(saddr), "l"(g) : "memory");
}
__device__ __forceinline__ void cpa_commit() {
    asm volatile("cp.async.commit_group;" ::: "memory");
}
__device__ __forceinline__ void cpa_wait1() {
    asm volatile("cp.async.wait_group 1;" ::: "memory");
}
__device__ __forceinline__ void cpa_wait0() {
    asm volatile("cp.async.wait_group 0;" ::: "memory");
}
#define LDSM4(r, addr) \
    asm volatile("ldmatrix.sync.aligned.m8n8.x4.shared.b16 {%0,%1,%2,%3}, [%4];" \
        : "=r"((r)[0]), "=r"((r)[1]), "=r"((r)[2]), "=r"((r)[3]) : "r"(addr))
#define MMA16816(c, a, b0, b1) \
    asm volatile("mma.sync.aligned.m16n8k16.row.col.f32.bf16.bf16.f32 " \
        "{%0,%1,%2,%3},{%4,%5,%6,%7},{%8,%9},{%0,%1,%2,%3};" \
        : "+f"((c)[0]), "+f"((c)[1]), "+f"((c)[2]), "+f"((c)[3]) \
        : "r"((a)[0]), "r"((a)[1]), "r"((a)[2]), "r"((a)[3]), "r"(b0), "r"(b1))

// ---------------------------------------------------------------------------
// fp32 -> bf16 hi/lo split
// ---------------------------------------------------------------------------
__global__ void conv_hilo(const float4* __restrict__ in, __nv_bfloat16* __restrict__ hi,
                          __nv_bfloat16* __restrict__ lo, int n4) {
    int stride = gridDim.x * blockDim.x;
    for (int i = blockIdx.x * blockDim.x + threadIdx.x; i < n4; i += stride) {
        float4 v = in[i];
        __nv_bfloat16 h0 = __float2bfloat16(v.x), h1 = __float2bfloat16(v.y);
        __nv_bfloat16 h2 = __float2bfloat16(v.z), h3 = __float2bfloat16(v.w);
        __nv_bfloat16 l0 = __float2bfloat16(v.x - __bfloat162float(h0));
        __nv_bfloat16 l1 = __float2bfloat16(v.y - __bfloat162float(h1));
        __nv_bfloat16 l2 = __float2bfloat16(v.z - __bfloat162float(h2));
        __nv_bfloat16 l3 = __float2bfloat16(v.w - __bfloat162float(h3));
        __nv_bfloat162* hp = (__nv_bfloat162*)(hi + (size_t)i * 4);
        __nv_bfloat162* lp = (__nv_bfloat162*)(lo + (size_t)i * 4);
        hp[0] = __halves2bfloat162(h0, h1);
        hp[1] = __halves2bfloat162(h2, h3);
        lp[0] = __halves2bfloat162(l0, l1);
        lp[1] = __halves2bfloat162(l2, l3);
    }
}

__global__ void build_bias(const float* __restrict__ qb, const float* __restrict__ vb) {
    int i = blockIdx.x * 256 + threadIdx.x;
    if (i < QKVN)
        g_bias[i] = (i < 512) ? qb[i] : ((i < 1024) ? 0.f : vb[i - 1024]);
}

// ---------------------------------------------------------------------------
// CPB MLP -> g_cpb[225][8]
// ---------------------------------------------------------------------------
__device__ __forceinline__ float signed_log_coord(int d) {
    float g = (float)d / 7.0f * 8.0f;
    float s = (g > 0.f) ? 1.f : ((g < 0.f) ? -1.f : 0.f);
    return s * log2f(fabsf(g) + 1.0f) / log2f(9.0f);
}
__global__ void cpb_kernel(const float* __restrict__ w1, const float* __restrict__ b1,
                           const float* __restrict__ w2) {
    int t = blockIdx.x;
    float c0 = signed_log_coord(t / 15 - 7);
    float c1 = signed_log_coord(t % 15 - 7);
    __shared__ float red[64][8];
    float p[8];
#pragma unroll
    for (int h = 0; h < 8; h++) p[h] = 0.f;
    for (int j = threadIdx.x; j < 512; j += 64) {
        float hx = fmaf(c0, w1[2 * j], fmaf(c1, w1[2 * j + 1], b1[j]));
        hx = fmaxf(hx, 0.f);
#pragma unroll
        for (int h = 0; h < 8; h++) p[h] += hx * w2[h * 512 + j];
    }
#pragma unroll
    for (int h = 0; h < 8; h++) red[threadIdx.x][h] = p[h];
    __syncthreads();
    if (threadIdx.x < 8) {
        float s = 0.f;
#pragma unroll
        for (int i = 0; i < 64; i++) s += red[i][threadIdx.x];
        g_cpb[t * 8 + threadIdx.x] = 16.f / (1.f + expf(-s));
    }
}

// ---------------------------------------------------------------------------
// HMMA GEMM: C[M,N] = (Ah+Al)[M,512] @ (Bh+Bl)[N,512]^T + bias[n]
// 3-term bf16 emulation via mma.sync.m16n8k16.
// Tile 128x128x32, 8 warps (2x4), warp tile 64x32, 3-stage cp.async.
// ---------------------------------------------------------------------------
#define LDT 80                       // padded smem row stride (bytes), 64 data + 16 pad
#define TILE_BYTES (128 * LDT)       // 10240
#define A_HI 0
#define A_LO TILE_BYTES
#define B_HI (2 * TILE_BYTES)
#define B_LO (3 * TILE_BYTES)
#define SS (4 * TILE_BYTES)          // 40960 per stage
#define GEMM_SMEM (3 * SS)           // 122880

__device__ __forceinline__ void load_stage(
    uint32_t sbase, int kt,
    const __nv_bfloat16* __restrict__ Ah, const __nv_bfloat16* __restrict__ Al,
    const __nv_bfloat16* __restrict__ Bh, const __nv_bfloat16* __restrict__ Bl,
    int m0, int n0, int tid) {
    const int k0 = kt * 32;
#pragma unroll
    for (int i = 0; i < 2; i++) {
        int id = tid + i * 256;
        int r = id >> 2, c = id & 3;
        uint32_t so = (uint32_t)(r * LDT + c * 16);
        size_t ga = (size_t)(m0 + r) * CDIM + k0 + c * 8;
        size_t gb = (size_t)(n0 + r) * CDIM + k0 + c * 8;
        cpa16(sbase + A_HI + so, Ah + ga);
        cpa16(sbase + A_LO + so, Al + ga);
        cpa16(sbase + B_HI + so, Bh + gb);
        cpa16(sbase + B_LO + so, Bl + gb);
    }
    cpa_commit();
}

__global__ void __launch_bounds__(256, 1)
gemm3bf16(const __nv_bfloat16* __restrict__ Ah, const __nv_bfloat16* __restrict__ Al,
          const __nv_bfloat16* __restrict__ Bh, const __nv_bfloat16* __restrict__ Bl,
          float* __restrict__ C, const float* __restrict__ bias, int ldc) {
    extern __shared__ char dsm[];
    const uint32_t smb = s2u(dsm);

    const int tid = threadIdx.x;
    const int wid = tid >> 5;
    const int lane = tid & 31;
    const int wm = wid >> 2;          // 0..1
    const int wn = wid & 3;           // 0..3
    const int m0 = blockIdx.y * 128;
    const int n0 = blockIdx.x * 128;

    float acc[16][4];
#pragma unroll
    for (int t = 0; t < 16; t++)
#pragma unroll
        for (int e = 0; e < 4; e++) acc[t][e] = 0.f;

    // prefetch stages 0,1
    load_stage(smb + 0 * SS, 0, Ah, Al, Bh, Bl, m0, n0, tid);
    load_stage(smb + 1 * SS, 1, Ah, Al, Bh, Bl, m0, n0, tid);

    // precomputed intra-tile offsets
    const uint32_t a_row = (uint32_t)((wm * 64 + (lane & 15)) * LDT + (lane >> 4) * 16);
    const uint32_t b_row = (uint32_t)((wn * 32 + (lane & 7) + ((lane >> 4) << 3)) * LDT
                                      + ((lane >> 3) & 1) * 16);

    const int NK = CDIM / 32;  // 16
    for (int kt = 0; kt < NK; kt++) {
        if (kt + 2 < NK) cpa_wait1(); else cpa_wait0();
        __syncthreads();
        if (kt + 2 < NK)
            load_stage(smb + (uint32_t)((kt + 2) % 3) * SS, kt + 2, Ah, Al, Bh, Bl, m0, n0, tid);

        const uint32_t st = smb + (uint32_t)(kt % 3) * SS;
#pragma unroll
        for (int ks = 0; ks < 2; ks++) {
            const uint32_t koff = (uint32_t)(ks * 32);
            uint32_t ah[4][4], al[4][4], bh[2][4], bl[2][4];
#pragma unroll
            for (int i = 0; i < 4; i++) {
                uint32_t ad = st + a_row + (uint32_t)(i * 16 * LDT) + koff;
                LDSM4(ah[i], ad + A_HI);
                LDSM4(al[i], ad + A_LO);
            }
#pragma unroll
            for (int nf = 0; nf < 2; nf++) {
                uint32_t bd = st + b_row + (uint32_t)(nf * 16 * LDT) + koff;
                LDSM4(bh[nf], bd + B_HI);
                LDSM4(bl[nf], bd + B_LO);
            }
#pragma unroll
            for (int i = 0; i < 4; i++) {
#pragma unroll
                for (int j = 0; j < 4; j++) {
                    float* c = acc[i * 4 + j];
                    int nf = j >> 1, sb = (j & 1) * 2;
                    MMA16816(c, ah[i], bh[nf][sb], bh[nf][sb + 1]);
                    MMA16816(c, ah[i], bl[nf][sb], bl[nf][sb + 1]);
                    MMA16816(c, al[i], bh[nf][sb], bh[nf][sb + 1]);
                }
            }
        }
    }

    // epilogue: direct stores with bias
#pragma unroll
    for (int i = 0; i < 4; i++) {
#pragma unroll
        for (int j = 0; j < 4; j++) {
            const float* c = acc[i * 4 + j];
            int row = m0 + wm * 64 + i * 16 + (lane >> 2);
            int col = n0 + wn * 32 + j * 8 + (lane & 3) * 2;
            float2 b2 = __ldg((const float2*)(bias + col));
            float2 v0 = make_float2(c[0] + b2.x, c[1] + b2.y);
            float2 v1 = make_float2(c[2] + b2.x, c[3] + b2.y);
            *(float2*)(C + (size_t)row * ldc + col) = v0;
            *(float2*)(C + (size_t)(row + 8) * ldc + col) = v1;
        }
    }
}

// ---------------------------------------------------------------------------
// Fused attention. grid=(1024,8), 256 threads.
// ---------------------------------------------------------------------------
#define AP 68
#define ATTN_SMEM ((4 * 64 * AP + 225) * sizeof(float))

__global__ void __launch_bounds__(256)
attn_kernel(const float* __restrict__ mask, const float* __restrict__ logit_scale) {
    const int b = blockIdx.x;
    const int h = blockIdx.y;
    extern __shared__ float smf[];
    float* sqT = smf;
    float* skT = smf + 64 * AP;
    float* sv  = smf + 2 * 64 * AP;
    float* sp  = smf + 3 * 64 * AP;
    float* scpb = smf + 4 * 64 * AP;

    const int tid = threadIdx.x;
    if (tid < 225) scpb[tid] = g_cpb[tid * 8 + h];

    const float* base = g_qkv + (size_t)b * NTOK * QKVN + h * HDIM;
#pragma unroll
    for (int it = 0; it < 4; it++) {
        int f = tid + it * 256;
        int n = f >> 4;
        int d4 = (f & 15) << 2;
        const float* rp = base + (size_t)n * QKVN + d4;
        float4 q4 = *(const float4*)(rp);
        float4 k4 = *(const float4*)(rp + CDIM);
        float4 v4 = *(const float4*)(rp + 2 * CDIM);
        float sq2 = q4.x * q4.x + q4.y * q4.y + q4.z * q4.z + q4.w * q4.w;
        float sk2 = k4.x * k4.x + k4.y * k4.y + k4.z * k4.z + k4.w * k4.w;
#pragma unroll
        for (int o = 8; o; o >>= 1) {
            sq2 += __shfl_xor_sync(0xffffffffu, sq2, o);
            sk2 += __shfl_xor_sync(0xffffffffu, sk2, o);
        }
        float qi = 1.0f / fmaxf(sqrtf(sq2), 1e-12f);
        float ki = 1.0f / fmaxf(sqrtf(sk2), 1e-12f);
        sqT[(d4 + 0) * AP + n] = q4.x * qi;
        sqT[(d4 + 1) * AP + n] = q4.y * qi;
        sqT[(d4 + 2) * AP + n] = q4.z * qi;
        sqT[(d4 + 3) * AP + n] = q4.w * qi;
        skT[(d4 + 0) * AP + n] = k4.x * ki;
        skT[(d4 + 1) * AP + n] = k4.y * ki;
        skT[(d4 + 2) * AP + n] = k4.z * ki;
        skT[(d4 + 3) * AP + n] = k4.w * ki;
        *(float4*)(sv + n * AP + d4) = v4;
    }
    __syncthreads();

    const float scale = expf(fminf(logit_scale[h], 4.605170185988091f));
    const int tx = tid & 15, ty = tid >> 4;
    const int i0 = ty * 4, j0 = tx * 4;

    float acc[4][4];
#pragma unroll
    for (int i = 0; i < 4; i++)
#pragma unroll
        for (int j = 0; j < 4; j++) acc[i][j] = 0.f;

    for (int kk = 0; kk < 64; kk++) {
        float4 a4 = *(const float4*)(sqT + kk * AP + i0);
        float4 b4 = *(const float4*)(skT + kk * AP + j0);
        float a[4] = {a4.x, a4.y, a4.z, a4.w};
        float bb[4] = {b4.x, b4.y, b4.z, b4.w};
#pragma unroll
        for (int i = 0; i < 4; i++)
#pragma unroll
            for (int j = 0; j < 4; j++) acc[i][j] = fmaf(a[i], bb[j], acc[i][j]);
    }

    const float* mrow = mask + (size_t)(b & 63) * NTOK * NTOK;
#pragma unroll
    for (int i = 0; i < 4; i++) {
        int I = i0 + i;
        float4 m4 = __ldg((const float4*)(mrow + I * 64 + j0));
        float mm[4] = {m4.x, m4.y, m4.z, m4.w};
#pragma unroll
        for (int j = 0; j < 4; j++) {
            int J = j0 + j;
            int t = ((I >> 3) - (J >> 3) + 7) * 15 + ((I & 7) - (J & 7) + 7);
            acc[i][j] = fmaf(acc[i][j], scale, scpb[t]) + mm[j];
        }
    }

#pragma unroll
    for (int i = 0; i < 4; i++) {
        float m = fmaxf(fmaxf(acc[i][0], acc[i][1]), fmaxf(acc[i][2], acc[i][3]));
#pragma unroll
        for (int o = 8; o; o >>= 1) m = fmaxf(m, __shfl_xor_sync(0xffffffffu, m, o));
        float e0 = __expf(acc[i][0] - m);
        float e1 = __expf(acc[i][1] - m);
        float e2 = __expf(acc[i][2] - m);
        float e3 = __expf(acc[i][3] - m);
        float s = e0 + e1 + e2 + e3;
#pragma unroll
        for (int o = 8; o; o >>= 1) s += __shfl_xor_sync(0xffffffffu, s, o);
        float inv = 1.f / s;
        acc[i][0] = e0 * inv; acc[i][1] = e1 * inv;
        acc[i][2] = e2 * inv; acc[i][3] = e3 * inv;
    }

#pragma unroll
    for (int j = 0; j < 4; j++) {
        *(float4*)(sp + (j0 + j) * AP + i0) =
            make_float4(acc[0][j], acc[1][j], acc[2][j], acc[3][j]);
    }
    __syncthreads();

    float o[4][4];
#pragma unroll
    for (int i = 0; i < 4; i++)
#pragma unroll
        for (int d = 0; d < 4; d++) o[i][d] = 0.f;

    for (int jj = 0; jj < 64; jj++) {
        float4 p4 = *(const float4*)(sp + jj * AP + i0);
        float4 v4 = *(const float4*)(sv + jj * AP + j0);
        float p[4] = {p4.x, p4.y, p4.z, p4.w};
        float vv[4] = {v4.x, v4.y, v4.z, v4.w};
#pragma unroll
        for (int i = 0; i < 4; i++)
#pragma unroll
            for (int d = 0; d < 4; d++) o[i][d] = fmaf(p[i], vv[d], o[i][d]);
    }

#pragma unroll
    for (int i = 0; i < 4; i++) {
        size_t off = ((size_t)(b * NTOK + i0 + i)) * CDIM + h * HDIM + j0;
        __nv_bfloat16 h0 = __float2bfloat16(o[i][0]);
        __nv_bfloat16 h1 = __float2bfloat16(o[i][1]);
        __nv_bfloat16 h2 = __float2bfloat16(o[i][2]);
        __nv_bfloat16 h3 = __float2bfloat16(o[i][3]);
        __nv_bfloat16 l0 = __float2bfloat16(o[i][0] - __bfloat162float(h0));
        __nv_bfloat16 l1 = __float2bfloat16(o[i][1] - __bfloat162float(h1));
        __nv_bfloat16 l2 = __float2bfloat16(o[i][2] - __bfloat162float(h2));
        __nv_bfloat16 l3 = __float2bfloat16(o[i][3] - __bfloat162float(h3));
        __nv_bfloat162* hp = (__nv_bfloat162*)(g_ahi + off);
        __nv_bfloat162* lp = (__nv_bfloat162*)(g_alo + off);
        hp[0] = __halves2bfloat162(h0, h1);
        hp[1] = __halves2bfloat162(h2, h3);
        lp[0] = __halves2bfloat162(l0, l1);
        lp[1] = __halves2bfloat162(l2, l3);
    }
}

// ---------------------------------------------------------------------------
// launch
// ---------------------------------------------------------------------------
extern "C" void kernel_launch(void* const* d_in, const int* in_sizes, int n_in,
                              void* d_out, int out_size) {
    const float* x           = (const float*)d_in[0];
    const float* mask        = (const float*)d_in[1];
    const float* qkv_w       = (const float*)d_in[2];
    const float* q_bias      = (const float*)d_in[3];
    const float* v_bias      = (const float*)d_in[4];
    const float* logit_scale = (const float*)d_in[5];
    const float* cpb_w1      = (const float*)d_in[6];
    const float* cpb_b1      = (const float*)d_in[7];
    const float* cpb_w2      = (const float*)d_in[8];
    const float* proj_w      = (const float*)d_in[9];
    const float* proj_b      = (const float*)d_in[10];
    float* out = (float*)d_out;

    float *qkv_p, *bias_p;
    __nv_bfloat16 *xhi, *xlo, *whi, *wlo, *phi, *plo, *ahi, *alo;
    cudaGetSymbolAddress((void**)&qkv_p, g_qkv);
    cudaGetSymbolAddress((void**)&bias_p, g_bias);
    cudaGetSymbolAddress((void**)&xhi, g_xhi);
    cudaGetSymbolAddress((void**)&xlo, g_xlo);
    cudaGetSymbolAddress((void**)&whi, g_whi);
    cudaGetSymbolAddress((void**)&wlo, g_wlo);
    cudaGetSymbolAddress((void**)&phi, g_phi);
    cudaGetSymbolAddress((void**)&plo, g_plo);
    cudaGetSymbolAddress((void**)&ahi, g_ahi);
    cudaGetSymbolAddress((void**)&alo, g_alo);

    cudaFuncSetAttribute(gemm3bf16, cudaFuncAttributeMaxDynamicSharedMemorySize, GEMM_SMEM);
    cudaFuncSetAttribute(attn_kernel, cudaFuncAttributeMaxDynamicSharedMemorySize, (int)ATTN_SMEM);

    // conversions
    conv_hilo<<<8192, 256>>>((const float4*)x, xhi, xlo, MTOT * CDIM / 4);
    conv_hilo<<<768, 256>>>((const float4*)qkv_w, whi, wlo, QKVN * CDIM / 4);
    conv_hilo<<<256, 256>>>((const float4*)proj_w, phi, plo, CDIM * CDIM / 4);
    build_bias<<<6, 256>>>(q_bias, v_bias);
    cpb_kernel<<<225, 64>>>(cpb_w1, cpb_b1, cpb_w2);

    // QKV projection: grid (N/128, M/128) = (12, 512)
    {
        dim3 grid(QKVN / 128, MTOT / 128);
        gemm3bf16<<<grid, 256, GEMM_SMEM>>>(xhi, xlo, whi, wlo, qkv_p, bias_p, QKVN);
    }

    // fused attention
    {
        dim3 grid(BATCH, NHEAD);
        attn_kernel<<<grid, 256, ATTN_SMEM>>>(mask, logit_scale);
    }

    // output projection -> d_out: grid (4, 512)
    {
        dim3 grid(CDIM / 128, MTOT / 128);
        gemm3bf16<<<grid, 256, GEMM_SMEM>>>(ahi, alo, phi, plo, out, proj_b, CDIM);
    }
}

// round 4
// speedup vs baseline: 4.1820x; 1.2362x over previous
#include <cuda_runtime.h>
#include <cuda_fp16.h>
#include <cstdint>

// ---------------------------------------------------------------------------
// Problem constants
// ---------------------------------------------------------------------------
#define BATCH 1024
#define NTOK  64
#define CDIM  512
#define NHEAD 8
#define HDIM  64
#define MTOT  (BATCH * NTOK)      // 65536
#define QKVN  (3 * CDIM)          // 1536

// ---------------------------------------------------------------------------
// Device-global scratch (allocation-free)
// ---------------------------------------------------------------------------
__device__ __align__(16) float   g_qkv[(size_t)MTOT * QKVN];
__device__ __align__(16) __half  g_xhi[(size_t)MTOT * CDIM];
__device__ __align__(16) __half  g_xlo[(size_t)MTOT * CDIM];
__device__ __align__(16) __half  g_wh[QKVN * CDIM];
__device__ __align__(16) __half  g_ph[CDIM * CDIM];
__device__ __align__(16) __half  g_ahi[(size_t)MTOT * CDIM];
__device__ __align__(16) __half  g_alo[(size_t)MTOT * CDIM];
__device__ __align__(16) float   g_bias[QKVN];
__device__ __align__(16) float   g_cpb[225 * 8];

// ---------------------------------------------------------------------------
// PTX helpers (baseline ISA: cp.async, ldmatrix, mma.sync fp16)
// ---------------------------------------------------------------------------
__device__ __forceinline__ uint32_t s2u(const void* p) {
    return (uint32_t)__cvta_generic_to_shared(p);
}
__device__ __forceinline__ void cpa16(uint32_t saddr, const void* g) {
    asm volatile("cp.async.cg.shared.global [%0], [%1], 16;" :: "r"(saddr), "l"(g) : "memory");
}
__device__ __forceinline__ void cpa_commit() {
    asm volatile("cp.async.commit_group;" ::: "memory");
}
__device__ __forceinline__ void cpa_wait1() {
    asm volatile("cp.async.wait_group 1;" ::: "memory");
}
__device__ __forceinline__ void cpa_wait0() {
    asm volatile("cp.async.wait_group 0;" ::: "memory");
}
#define LDSM4(r, addr) \
    asm volatile("ldmatrix.sync.aligned.m8n8.x4.shared.b16 {%0,%1,%2,%3}, [%4];" \
        : "=r"((r)[0]), "=r"((r)[1]), "=r"((r)[2]), "=r"((r)[3]) : "r"(addr))
#define MMAH16816(c, a, b0, b1) \
    asm volatile("mma.sync.aligned.m16n8k16.row.col.f32.f16.f16.f32 " \
        "{%0,%1,%2,%3},{%4,%5,%6,%7},{%8,%9},{%0,%1,%2,%3};" \
        : "+f"((c)[0]), "+f"((c)[1]), "+f"((c)[2]), "+f"((c)[3]) \
        : "r"((a)[0]), "r"((a)[1]), "r"((a)[2]), "r"((a)[3]), "r"(b0), "r"(b1))

// ---------------------------------------------------------------------------
// fp32 -> fp16 hi/lo split ; fp32 -> fp16 single
// ---------------------------------------------------------------------------
__global__ void conv_hilo_h(const float4* __restrict__ in, __half* __restrict__ hi,
                            __half* __restrict__ lo, int n4) {
    int stride = gridDim.x * blockDim.x;
    for (int i = blockIdx.x * blockDim.x + threadIdx.x; i < n4; i += stride) {
        float4 v = in[i];
        __half h0 = __float2half(v.x), h1 = __float2half(v.y);
        __half h2 = __float2half(v.z), h3 = __float2half(v.w);
        __half l0 = __float2half(v.x - __half2float(h0));
        __half l1 = __float2half(v.y - __half2float(h1));
        __half l2 = __float2half(v.z - __half2float(h2));
        __half l3 = __float2half(v.w - __half2float(h3));
        __half2* hp = (__half2*)(hi + (size_t)i * 4);
        __half2* lp = (__half2*)(lo + (size_t)i * 4);
        hp[0] = __halves2half2(h0, h1);
        hp[1] = __halves2half2(h2, h3);
        lp[0] = __halves2half2(l0, l1);
        lp[1] = __halves2half2(l2, l3);
    }
}

__global__ void conv_h(const float4* __restrict__ in, __half* __restrict__ out, int n4) {
    int stride = gridDim.x * blockDim.x;
    for (int i = blockIdx.x * blockDim.x + threadIdx.x; i < n4; i += stride) {
        float4 v = in[i];
        __half2* op = (__half2*)(out + (size_t)i * 4);
        op[0] = __halves2half2(__float2half(v.x), __float2half(v.y));
        op[1] = __halves2half2(__float2half(v.z), __float2half(v.w));
    }
}

__global__ void build_bias(const float* __restrict__ qb, const float* __restrict__ vb) {
    int i = blockIdx.x * 256 + threadIdx.x;
    if (i < QKVN)
        g_bias[i] = (i < 512) ? qb[i] : ((i < 1024) ? 0.f : vb[i - 1024]);
}

// ---------------------------------------------------------------------------
// CPB MLP -> g_cpb[225][8]
// ---------------------------------------------------------------------------
__device__ __forceinline__ float signed_log_coord(int d) {
    float g = (float)d / 7.0f * 8.0f;
    float s = (g > 0.f) ? 1.f : ((g < 0.f) ? -1.f : 0.f);
    return s * log2f(fabsf(g) + 1.0f) / log2f(9.0f);
}
__global__ void cpb_kernel(const float* __restrict__ w1, const float* __restrict__ b1,
                           const float* __restrict__ w2) {
    int t = blockIdx.x;
    float c0 = signed_log_coord(t / 15 - 7);
    float c1 = signed_log_coord(t % 15 - 7);
    __shared__ float red[64][8];
    float p[8];
#pragma unroll
    for (int h = 0; h < 8; h++) p[h] = 0.f;
    for (int j = threadIdx.x; j < 512; j += 64) {
        float hx = fmaf(c0, w1[2 * j], fmaf(c1, w1[2 * j + 1], b1[j]));
        hx = fmaxf(hx, 0.f);
#pragma unroll
        for (int h = 0; h < 8; h++) p[h] += hx * w2[h * 512 + j];
    }
#pragma unroll
    for (int h = 0; h < 8; h++) red[threadIdx.x][h] = p[h];
    __syncthreads();
    if (threadIdx.x < 8) {
        float s = 0.f;
#pragma unroll
        for (int i = 0; i < 64; i++) s += red[i][threadIdx.x];
        g_cpb[t * 8 + threadIdx.x] = 16.f / (1.f + expf(-s));
    }
}

// ---------------------------------------------------------------------------
// HMMA GEMM (fp16 2-pass): C[M,N] = (Ah+Al)[M,512] @ B[N,512]^T + bias[n]
// Tile 128x128x32, 8 warps (2x4), warp tile 64x32, 3-stage cp.async.
// ---------------------------------------------------------------------------
#define LDT 80                       // padded smem row stride (bytes)
#define TILE_BYTES (128 * LDT)       // 10240
#define A_HI 0
#define A_LO TILE_BYTES
#define B_OF (2 * TILE_BYTES)
#define SS (3 * TILE_BYTES)          // 30720 per stage
#define GEMM_SMEM (3 * SS)           // 92160

__device__ __forceinline__ void load_stage(
    uint32_t sbase, int kt,
    const __half* __restrict__ Ah, const __half* __restrict__ Al,
    const __half* __restrict__ B,
    int m0, int n0, int tid) {
    const int k0 = kt * 32;
#pragma unroll
    for (int i = 0; i < 2; i++) {
        int id = tid + i * 256;
        int r = id >> 2, c = id & 3;
        uint32_t so = (uint32_t)(r * LDT + c * 16);
        size_t ga = (size_t)(m0 + r) * CDIM + k0 + c * 8;
        size_t gb = (size_t)(n0 + r) * CDIM + k0 + c * 8;
        cpa16(sbase + A_HI + so, Ah + ga);
        cpa16(sbase + A_LO + so, Al + ga);
        cpa16(sbase + B_OF + so, B + gb);
    }
    cpa_commit();
}

__global__ void __launch_bounds__(256, 1)
gemm2h(const __half* __restrict__ Ah, const __half* __restrict__ Al,
       const __half* __restrict__ B,
       float* __restrict__ C, const float* __restrict__ bias, int ldc) {
    extern __shared__ char dsm[];
    const uint32_t smb = s2u(dsm);

    const int tid = threadIdx.x;
    const int wid = tid >> 5;
    const int lane = tid & 31;
    const int wm = wid >> 2;          // 0..1
    const int wn = wid & 3;           // 0..3
    const int m0 = blockIdx.y * 128;
    const int n0 = blockIdx.x * 128;

    float acc[16][4];
#pragma unroll
    for (int t = 0; t < 16; t++)
#pragma unroll
        for (int e = 0; e < 4; e++) acc[t][e] = 0.f;

    load_stage(smb + 0 * SS, 0, Ah, Al, B, m0, n0, tid);
    load_stage(smb + 1 * SS, 1, Ah, Al, B, m0, n0, tid);

    const uint32_t a_row = (uint32_t)((wm * 64 + (lane & 15)) * LDT + (lane >> 4) * 16);
    const uint32_t b_row = (uint32_t)((wn * 32 + (lane & 7) + ((lane >> 4) << 3)) * LDT
                                      + ((lane >> 3) & 1) * 16);

    const int NK = CDIM / 32;  // 16
    for (int kt = 0; kt < NK; kt++) {
        if (kt + 2 < NK) cpa_wait1(); else cpa_wait0();
        __syncthreads();
        if (kt + 2 < NK)
            load_stage(smb + (uint32_t)((kt + 2) % 3) * SS, kt + 2, Ah, Al, B, m0, n0, tid);

        const uint32_t st = smb + (uint32_t)(kt % 3) * SS;
#pragma unroll
        for (int ks = 0; ks < 2; ks++) {
            const uint32_t koff = (uint32_t)(ks * 32);
            uint32_t ah[4][4], al[4][4], bh[2][4];
#pragma unroll
            for (int i = 0; i < 4; i++) {
                uint32_t ad = st + a_row + (uint32_t)(i * 16 * LDT) + koff;
                LDSM4(ah[i], ad + A_HI);
                LDSM4(al[i], ad + A_LO);
            }
#pragma unroll
            for (int nf = 0; nf < 2; nf++) {
                uint32_t bd = st + b_row + (uint32_t)(nf * 16 * LDT) + koff;
                LDSM4(bh[nf], bd + B_OF);
            }
#pragma unroll
            for (int i = 0; i < 4; i++) {
#pragma unroll
                for (int j = 0; j < 4; j++) {
                    float* c = acc[i * 4 + j];
                    int nf = j >> 1, sb = (j & 1) * 2;
                    MMAH16816(c, ah[i], bh[nf][sb], bh[nf][sb + 1]);
                    MMAH16816(c, al[i], bh[nf][sb], bh[nf][sb + 1]);
                }
            }
        }
    }

    // epilogue: direct stores with bias
#pragma unroll
    for (int i = 0; i < 4; i++) {
#pragma unroll
        for (int j = 0; j < 4; j++) {
            const float* c = acc[i * 4 + j];
            int row = m0 + wm * 64 + i * 16 + (lane >> 2);
            int col = n0 + wn * 32 + j * 8 + (lane & 3) * 2;
            float2 b2 = __ldg((const float2*)(bias + col));
            float2 v0 = make_float2(c[0] + b2.x, c[1] + b2.y);
            float2 v1 = make_float2(c[2] + b2.x, c[3] + b2.y);
            *(float2*)(C + (size_t)row * ldc + col) = v0;
            *(float2*)(C + (size_t)(row + 8) * ldc + col) = v1;
        }
    }
}

// ---------------------------------------------------------------------------
// Fused attention. grid=(1024,8), 256 threads.
// ---------------------------------------------------------------------------
#define AP 68
#define ATTN_SMEM ((4 * 64 * AP + 225) * sizeof(float))

__global__ void __launch_bounds__(256)
attn_kernel(const float* __restrict__ mask, const float* __restrict__ logit_scale) {
    const int b = blockIdx.x;
    const int h = blockIdx.y;
    extern __shared__ float smf[];
    float* sqT = smf;
    float* skT = smf + 64 * AP;
    float* sv  = smf + 2 * 64 * AP;
    float* sp  = smf + 3 * 64 * AP;
    float* scpb = smf + 4 * 64 * AP;

    const int tid = threadIdx.x;
    if (tid < 225) scpb[tid] = g_cpb[tid * 8 + h];

    const float* base = g_qkv + (size_t)b * NTOK * QKVN + h * HDIM;
#pragma unroll
    for (int it = 0; it < 4; it++) {
        int f = tid + it * 256;
        int n = f >> 4;
        int d4 = (f & 15) << 2;
        const float* rp = base + (size_t)n * QKVN + d4;
        float4 q4 = *(const float4*)(rp);
        float4 k4 = *(const float4*)(rp + CDIM);
        float4 v4 = *(const float4*)(rp + 2 * CDIM);
        float sq2 = q4.x * q4.x + q4.y * q4.y + q4.z * q4.z + q4.w * q4.w;
        float sk2 = k4.x * k4.x + k4.y * k4.y + k4.z * k4.z + k4.w * k4.w;
#pragma unroll
        for (int o = 8; o; o >>= 1) {
            sq2 += __shfl_xor_sync(0xffffffffu, sq2, o);
            sk2 += __shfl_xor_sync(0xffffffffu, sk2, o);
        }
        float qi = 1.0f / fmaxf(sqrtf(sq2), 1e-12f);
        float ki = 1.0f / fmaxf(sqrtf(sk2), 1e-12f);
        sqT[(d4 + 0) * AP + n] = q4.x * qi;
        sqT[(d4 + 1) * AP + n] = q4.y * qi;
        sqT[(d4 + 2) * AP + n] = q4.z * qi;
        sqT[(d4 + 3) * AP + n] = q4.w * qi;
        skT[(d4 + 0) * AP + n] = k4.x * ki;
        skT[(d4 + 1) * AP + n] = k4.y * ki;
        skT[(d4 + 2) * AP + n] = k4.z * ki;
        skT[(d4 + 3) * AP + n] = k4.w * ki;
        *(float4*)(sv + n * AP + d4) = v4;
    }
    __syncthreads();

    const float scale = expf(fminf(logit_scale[h], 4.605170185988091f));
    const int tx = tid & 15, ty = tid >> 4;
    const int i0 = ty * 4, j0 = tx * 4;

    float acc[4][4];
#pragma unroll
    for (int i = 0; i < 4; i++)
#pragma unroll
        for (int j = 0; j < 4; j++) acc[i][j] = 0.f;

    for (int kk = 0; kk < 64; kk++) {
        float4 a4 = *(const float4*)(sqT + kk * AP + i0);
        float4 b4 = *(const float4*)(skT + kk * AP + j0);
        float a[4] = {a4.x, a4.y, a4.z, a4.w};
        float bb[4] = {b4.x, b4.y, b4.z, b4.w};
#pragma unroll
        for (int i = 0; i < 4; i++)
#pragma unroll
            for (int j = 0; j < 4; j++) acc[i][j] = fmaf(a[i], bb[j], acc[i][j]);
    }

    const float* mrow = mask + (size_t)(b & 63) * NTOK * NTOK;
#pragma unroll
    for (int i = 0; i < 4; i++) {
        int I = i0 + i;
        float4 m4 = __ldg((const float4*)(mrow + I * 64 + j0));
        float mm[4] = {m4.x, m4.y, m4.z, m4.w};
#pragma unroll
        for (int j = 0; j < 4; j++) {
            int J = j0 + j;
            int t = ((I >> 3) - (J >> 3) + 7) * 15 + ((I & 7) - (J & 7) + 7);
            acc[i][j] = fmaf(acc[i][j], scale, scpb[t]) + mm[j];
        }
    }

#pragma unroll
    for (int i = 0; i < 4; i++) {
        float m = fmaxf(fmaxf(acc[i][0], acc[i][1]), fmaxf(acc[i][2], acc[i][3]));
#pragma unroll
        for (int o = 8; o; o >>= 1) m = fmaxf(m, __shfl_xor_sync(0xffffffffu, m, o));
        float e0 = __expf(acc[i][0] - m);
        float e1 = __expf(acc[i][1] - m);
        float e2 = __expf(acc[i][2] - m);
        float e3 = __expf(acc[i][3] - m);
        float s = e0 + e1 + e2 + e3;
#pragma unroll
        for (int o = 8; o; o >>= 1) s += __shfl_xor_sync(0xffffffffu, s, o);
        float inv = 1.f / s;
        acc[i][0] = e0 * inv; acc[i][1] = e1 * inv;
        acc[i][2] = e2 * inv; acc[i][3] = e3 * inv;
    }

#pragma unroll
    for (int j = 0; j < 4; j++) {
        *(float4*)(sp + (j0 + j) * AP + i0) =
            make_float4(acc[0][j], acc[1][j], acc[2][j], acc[3][j]);
    }
    __syncthreads();

    float o[4][4];
#pragma unroll
    for (int i = 0; i < 4; i++)
#pragma unroll
        for (int d = 0; d < 4; d++) o[i][d] = 0.f;

    for (int jj = 0; jj < 64; jj++) {
        float4 p4 = *(const float4*)(sp + jj * AP + i0);
        float4 v4 = *(const float4*)(sv + jj * AP + j0);
        float p[4] = {p4.x, p4.y, p4.z, p4.w};
        float vv[4] = {v4.x, v4.y, v4.z, v4.w};
#pragma unroll
        for (int i = 0; i < 4; i++)
#pragma unroll
            for (int d = 0; d < 4; d++) o[i][d] = fmaf(p[i], vv[d], o[i][d]);
    }

    // write fp16 hi/lo (input to proj GEMM)
#pragma unroll
    for (int i = 0; i < 4; i++) {
        size_t off = ((size_t)(b * NTOK + i0 + i)) * CDIM + h * HDIM + j0;
        __half h0 = __float2half(o[i][0]);
        __half h1 = __float2half(o[i][1]);
        __half h2 = __float2half(o[i][2]);
        __half h3 = __float2half(o[i][3]);
        __half l0 = __float2half(o[i][0] - __half2float(h0));
        __half l1 = __float2half(o[i][1] - __half2float(h1));
        __half l2 = __float2half(o[i][2] - __half2float(h2));
        __half l3 = __float2half(o[i][3] - __half2float(h3));
        __half2* hp = (__half2*)(g_ahi + off);
        __half2* lp = (__half2*)(g_alo + off);
        hp[0] = __halves2half2(h0, h1);
        hp[1] = __halves2half2(h2, h3);
        lp[0] = __halves2half2(l0, l1);
        lp[1] = __halves2half2(l2, l3);
    }
}

// ---------------------------------------------------------------------------
// launch
// ---------------------------------------------------------------------------
extern "C" void kernel_launch(void* const* d_in, const int* in_sizes, int n_in,
                              void* d_out, int out_size) {
    const float* x           = (const float*)d_in[0];
    const float* mask        = (const float*)d_in[1];
    const float* qkv_w       = (const float*)d_in[2];
    const float* q_bias      = (const float*)d_in[3];
    const float* v_bias      = (const float*)d_in[4];
    const float* logit_scale = (const float*)d_in[5];
    const float* cpb_w1      = (const float*)d_in[6];
    const float* cpb_b1      = (const float*)d_in[7];
    const float* cpb_w2      = (const float*)d_in[8];
    const float* proj_w      = (const float*)d_in[9];
    const float* proj_b      = (const float*)d_in[10];
    float* out = (float*)d_out;

    float *qkv_p, *bias_p;
    __half *xhi, *xlo, *wh, *ph, *ahi, *alo;
    cudaGetSymbolAddress((void**)&qkv_p, g_qkv);
    cudaGetSymbolAddress((void**)&bias_p, g_bias);
    cudaGetSymbolAddress((void**)&xhi, g_xhi);
    cudaGetSymbolAddress((void**)&xlo, g_xlo);
    cudaGetSymbolAddress((void**)&wh, g_wh);
    cudaGetSymbolAddress((void**)&ph, g_ph);
    cudaGetSymbolAddress((void**)&ahi, g_ahi);
    cudaGetSymbolAddress((void**)&alo, g_alo);

    cudaFuncSetAttribute(gemm2h, cudaFuncAttributeMaxDynamicSharedMemorySize, GEMM_SMEM);
    cudaFuncSetAttribute(attn_kernel, cudaFuncAttributeMaxDynamicSharedMemorySize, (int)ATTN_SMEM);

    // conversions
    conv_hilo_h<<<8192, 256>>>((const float4*)x, xhi, xlo, MTOT * CDIM / 4);
    conv_h<<<768, 256>>>((const float4*)qkv_w, wh, QKVN * CDIM / 4);
    conv_h<<<256, 256>>>((const float4*)proj_w, ph, CDIM * CDIM / 4);
    build_bias<<<6, 256>>>(q_bias, v_bias);
    cpb_kernel<<<225, 64>>>(cpb_w1, cpb_b1, cpb_w2);

    // QKV projection: grid (12, 512)
    {
        dim3 grid(QKVN / 128, MTOT / 128);
        gemm2h<<<grid, 256, GEMM_SMEM>>>(xhi, xlo, wh, qkv_p, bias_p, QKVN);
    }

    // fused attention
    {
        dim3 grid(BATCH, NHEAD);
        attn_kernel<<<grid, 256, ATTN_SMEM>>>(mask, logit_scale);
    }

    // output projection -> d_out: grid (4, 512)
    {
        dim3 grid(CDIM / 128, MTOT / 128);
        gemm2h<<<grid, 256, GEMM_SMEM>>>(ahi, alo, ph, out, proj_b, CDIM);
    }
}

// round 5
// speedup vs baseline: 4.3128x; 1.0313x over previous
#include <cuda_runtime.h>
#include <cuda_fp16.h>
#include <cstdint>

// ---------------------------------------------------------------------------
// Problem constants
// ---------------------------------------------------------------------------
#define BATCH 1024
#define NTOK  64
#define CDIM  512
#define NHEAD 8
#define HDIM  64
#define MTOT  (BATCH * NTOK)      // 65536
#define QKVN  (3 * CDIM)          // 1536

// ---------------------------------------------------------------------------
// Device-global scratch (allocation-free)
// ---------------------------------------------------------------------------
__device__ __align__(16) __half  g_qkvh[(size_t)MTOT * QKVN];   // fp16 qkv
__device__ __align__(16) __half  g_xhi[(size_t)MTOT * CDIM];
__device__ __align__(16) __half  g_xlo[(size_t)MTOT * CDIM];
__device__ __align__(16) __half  g_wh[QKVN * CDIM];
__device__ __align__(16) __half  g_ph[CDIM * CDIM];
__device__ __align__(16) __half  g_ahi[(size_t)MTOT * CDIM];
__device__ __align__(16) __half  g_alo[(size_t)MTOT * CDIM];
__device__ __align__(16) float   g_bias[QKVN];
__device__ __align__(16) float   g_cpb[225 * 8];

// ---------------------------------------------------------------------------
// PTX helpers
// ---------------------------------------------------------------------------
__device__ __forceinline__ uint32_t s2u(const void* p) {
    return (uint32_t)__cvta_generic_to_shared(p);
}
__device__ __forceinline__ void cpa16(uint32_t saddr, const void* g) {
    asm volatile("cp.async.cg.shared.global [%0], [%1], 16;" :: "r"(saddr), "l"(g) : "memory");
}
__device__ __forceinline__ void cpa_commit() {
    asm volatile("cp.async.commit_group;" ::: "memory");
}
__device__ __forceinline__ void cpa_wait1() {
    asm volatile("cp.async.wait_group 1;" ::: "memory");
}
__device__ __forceinline__ void cpa_wait0() {
    asm volatile("cp.async.wait_group 0;" ::: "memory");
}
#define LDSM4(r, addr) \
    asm volatile("ldmatrix.sync.aligned.m8n8.x4.shared.b16 {%0,%1,%2,%3}, [%4];" \
        : "=r"((r)[0]), "=r"((r)[1]), "=r"((r)[2]), "=r"((r)[3]) : "r"(addr))
#define MMAH16816(c, a, b0, b1) \
    asm volatile("mma.sync.aligned.m16n8k16.row.col.f32.f16.f16.f32 " \
        "{%0,%1,%2,%3},{%4,%5,%6,%7},{%8,%9},{%0,%1,%2,%3};" \
        : "+f"((c)[0]), "+f"((c)[1]), "+f"((c)[2]), "+f"((c)[3]) \
        : "r"((a)[0]), "r"((a)[1]), "r"((a)[2]), "r"((a)[3]), "r"(b0), "r"(b1))

// f32x2 packed fp32 math (B300: 2x fp32 FMA throughput)
__device__ __forceinline__ unsigned long long pack2(float x, float y) {
    unsigned long long r;
    asm("mov.b64 %0, {%1, %2};" : "=l"(r) : "r"(__float_as_uint(x)), "r"(__float_as_uint(y)));
    return r;
}
__device__ __forceinline__ void fma2(unsigned long long& d, unsigned long long a, unsigned long long b) {
    asm("fma.rn.f32x2 %0, %1, %2, %0;" : "+l"(d) : "l"(a), "l"(b));
}
__device__ __forceinline__ void unpack2(unsigned long long v, float& x, float& y) {
    unsigned int lo, hi;
    asm("mov.b64 {%0, %1}, %2;" : "=r"(lo), "=r"(hi) : "l"(v));
    x = __uint_as_float(lo); y = __uint_as_float(hi);
}

// ---------------------------------------------------------------------------
// fp32 -> fp16 hi/lo split (x)
// ---------------------------------------------------------------------------
__global__ void conv_hilo_h(const float4* __restrict__ in, __half* __restrict__ hi,
                            __half* __restrict__ lo, int n4) {
    int stride = gridDim.x * blockDim.x;
    for (int i = blockIdx.x * blockDim.x + threadIdx.x; i < n4; i += stride) {
        float4 v = in[i];
        __half h0 = __float2half(v.x), h1 = __float2half(v.y);
        __half h2 = __float2half(v.z), h3 = __float2half(v.w);
        __half l0 = __float2half(v.x - __half2float(h0));
        __half l1 = __float2half(v.y - __half2float(h1));
        __half l2 = __float2half(v.z - __half2float(h2));
        __half l3 = __float2half(v.w - __half2float(h3));
        __half2* hp = (__half2*)(hi + (size_t)i * 4);
        __half2* lp = (__half2*)(lo + (size_t)i * 4);
        hp[0] = __halves2half2(h0, h1);
        hp[1] = __halves2half2(h2, h3);
        lp[0] = __halves2half2(l0, l1);
        lp[1] = __halves2half2(l2, l3);
    }
}

// both weight conversions in one launch
__global__ void conv_h2(const float4* __restrict__ w, __half* __restrict__ wh, int n4w,
                        const float4* __restrict__ p, __half* __restrict__ ph, int n4p) {
    int stride = gridDim.x * blockDim.x;
    int total = n4w + n4p;
    for (int i = blockIdx.x * blockDim.x + threadIdx.x; i < total; i += stride) {
        const float4* src; __half* dst; int idx;
        if (i < n4w) { src = w; dst = wh; idx = i; }
        else         { src = p; dst = ph; idx = i - n4w; }
        float4 v = src[idx];
        __half2* op = (__half2*)(dst + (size_t)idx * 4);
        op[0] = __halves2half2(__float2half(v.x), __float2half(v.y));
        op[1] = __halves2half2(__float2half(v.z), __float2half(v.w));
    }
}

// ---------------------------------------------------------------------------
// CPB MLP + bias build in one launch
// ---------------------------------------------------------------------------
__device__ __forceinline__ float signed_log_coord(int d) {
    float g = (float)d / 7.0f * 8.0f;
    float s = (g > 0.f) ? 1.f : ((g < 0.f) ? -1.f : 0.f);
    return s * log2f(fabsf(g) + 1.0f) / log2f(9.0f);
}
__global__ void cpb_bias_kernel(const float* __restrict__ w1, const float* __restrict__ b1,
                                const float* __restrict__ w2,
                                const float* __restrict__ qb, const float* __restrict__ vb) {
    int t = blockIdx.x;
    if (t >= 225) {  // bias blocks: 225..248, 64 threads each
        int i = (t - 225) * 64 + threadIdx.x;
        if (threadIdx.x < 64 && i < QKVN)
            g_bias[i] = (i < 512) ? qb[i] : ((i < 1024) ? 0.f : vb[i - 1024]);
        return;
    }
    float c0 = signed_log_coord(t / 15 - 7);
    float c1 = signed_log_coord(t % 15 - 7);
    __shared__ float red[64][8];
    float p[8];
#pragma unroll
    for (int h = 0; h < 8; h++) p[h] = 0.f;
    for (int j = threadIdx.x; j < 512; j += 64) {
        float hx = fmaf(c0, w1[2 * j], fmaf(c1, w1[2 * j + 1], b1[j]));
        hx = fmaxf(hx, 0.f);
#pragma unroll
        for (int h = 0; h < 8; h++) p[h] += hx * w2[h * 512 + j];
    }
#pragma unroll
    for (int h = 0; h < 8; h++) red[threadIdx.x][h] = p[h];
    __syncthreads();
    if (threadIdx.x < 8) {
        float s = 0.f;
#pragma unroll
        for (int i = 0; i < 64; i++) s += red[i][threadIdx.x];
        g_cpb[t * 8 + threadIdx.x] = 16.f / (1.f + expf(-s));
    }
}

// ---------------------------------------------------------------------------
// HMMA GEMM (fp16 2-pass): C[M,N] = (Ah+Al)[M,512] @ B[N,512]^T + bias[n]
// Tile 128x128x32, 8 warps (2x4), 3-stage cp.async. HALF_OUT selects fp16/fp32 C.
// ---------------------------------------------------------------------------
#define LDT 80
#define TILE_BYTES (128 * LDT)
#define A_HI 0
#define A_LO TILE_BYTES
#define B_OF (2 * TILE_BYTES)
#define SS (3 * TILE_BYTES)          // 30720 per stage
#define GEMM_SMEM (3 * SS)           // 92160

__device__ __forceinline__ void load_stage(
    uint32_t sbase, int kt,
    const __half* __restrict__ Ah, const __half* __restrict__ Al,
    const __half* __restrict__ B,
    int m0, int n0, int tid) {
    const int k0 = kt * 32;
#pragma unroll
    for (int i = 0; i < 2; i++) {
        int id = tid + i * 256;
        int r = id >> 2, c = id & 3;
        uint32_t so = (uint32_t)(r * LDT + c * 16);
        size_t ga = (size_t)(m0 + r) * CDIM + k0 + c * 8;
        size_t gb = (size_t)(n0 + r) * CDIM + k0 + c * 8;
        cpa16(sbase + A_HI + so, Ah + ga);
        cpa16(sbase + A_LO + so, Al + ga);
        cpa16(sbase + B_OF + so, B + gb);
    }
    cpa_commit();
}

template <bool HALF_OUT>
__global__ void __launch_bounds__(256, 1)
gemm2h(const __half* __restrict__ Ah, const __half* __restrict__ Al,
       const __half* __restrict__ B,
       float* __restrict__ Cf, __half* __restrict__ Ch,
       const float* __restrict__ bias, int ldc) {
    extern __shared__ char dsm[];
    const uint32_t smb = s2u(dsm);

    const int tid = threadIdx.x;
    const int wid = tid >> 5;
    const int lane = tid & 31;
    const int wm = wid >> 2;
    const int wn = wid & 3;
    const int m0 = blockIdx.y * 128;
    const int n0 = blockIdx.x * 128;

    float acc[16][4];
#pragma unroll
    for (int t = 0; t < 16; t++)
#pragma unroll
        for (int e = 0; e < 4; e++) acc[t][e] = 0.f;

    load_stage(smb + 0 * SS, 0, Ah, Al, B, m0, n0, tid);
    load_stage(smb + 1 * SS, 1, Ah, Al, B, m0, n0, tid);

    const uint32_t a_row = (uint32_t)((wm * 64 + (lane & 15)) * LDT + (lane >> 4) * 16);
    const uint32_t b_row = (uint32_t)((wn * 32 + (lane & 7) + ((lane >> 4) << 3)) * LDT
                                      + ((lane >> 3) & 1) * 16);

    const int NK = CDIM / 32;  // 16
    for (int kt = 0; kt < NK; kt++) {
        if (kt + 2 < NK) cpa_wait1(); else cpa_wait0();
        __syncthreads();
        if (kt + 2 < NK)
            load_stage(smb + (uint32_t)((kt + 2) % 3) * SS, kt + 2, Ah, Al, B, m0, n0, tid);

        const uint32_t st = smb + (uint32_t)(kt % 3) * SS;
#pragma unroll
        for (int ks = 0; ks < 2; ks++) {
            const uint32_t koff = (uint32_t)(ks * 32);
            uint32_t ah[4][4], al[4][4], bh[2][4];
#pragma unroll
            for (int i = 0; i < 4; i++) {
                uint32_t ad = st + a_row + (uint32_t)(i * 16 * LDT) + koff;
                LDSM4(ah[i], ad + A_HI);
                LDSM4(al[i], ad + A_LO);
            }
#pragma unroll
            for (int nf = 0; nf < 2; nf++) {
                uint32_t bd = st + b_row + (uint32_t)(nf * 16 * LDT) + koff;
                LDSM4(bh[nf], bd + B_OF);
            }
#pragma unroll
            for (int i = 0; i < 4; i++) {
#pragma unroll
                for (int j = 0; j < 4; j++) {
                    float* c = acc[i * 4 + j];
                    int nf = j >> 1, sb = (j & 1) * 2;
                    MMAH16816(c, ah[i], bh[nf][sb], bh[nf][sb + 1]);
                    MMAH16816(c, al[i], bh[nf][sb], bh[nf][sb + 1]);
                }
            }
        }
    }

#pragma unroll
    for (int i = 0; i < 4; i++) {
#pragma unroll
        for (int j = 0; j < 4; j++) {
            const float* c = acc[i * 4 + j];
            int row = m0 + wm * 64 + i * 16 + (lane >> 2);
            int col = n0 + wn * 32 + j * 8 + (lane & 3) * 2;
            float2 b2 = __ldg((const float2*)(bias + col));
            if (HALF_OUT) {
                __half2 v0 = __floats2half2_rn(c[0] + b2.x, c[1] + b2.y);
                __half2 v1 = __floats2half2_rn(c[2] + b2.x, c[3] + b2.y);
                *(__half2*)(Ch + (size_t)row * ldc + col) = v0;
                *(__half2*)(Ch + (size_t)(row + 8) * ldc + col) = v1;
            } else {
                float2 v0 = make_float2(c[0] + b2.x, c[1] + b2.y);
                float2 v1 = make_float2(c[2] + b2.x, c[3] + b2.y);
                *(float2*)(Cf + (size_t)row * ldc + col) = v0;
                *(float2*)(Cf + (size_t)(row + 8) * ldc + col) = v1;
            }
        }
    }
}

// ---------------------------------------------------------------------------
// Fused attention. grid=(1024,8), 256 threads. fp16 qkv in, f32x2 math.
// ---------------------------------------------------------------------------
#define AP 68
#define ATTN_SMEM ((4 * 64 * AP + 225) * sizeof(float))

__global__ void __launch_bounds__(256)
attn_kernel(const float* __restrict__ mask, const float* __restrict__ logit_scale) {
    const int b = blockIdx.x;
    const int h = blockIdx.y;
    extern __shared__ float smf[];
    float* sqT = smf;                 // [64][AP] q transposed [d][n]
    float* skT = smf + 64 * AP;
    float* sv  = smf + 2 * 64 * AP;   // [n][d]
    float* sp  = smf + 3 * 64 * AP;   // P transposed [j][i]
    float* scpb = smf + 4 * 64 * AP;

    const int tid = threadIdx.x;
    if (tid < 225) scpb[tid] = g_cpb[tid * 8 + h];

    const __half* base = g_qkvh + (size_t)b * NTOK * QKVN + h * HDIM;
#pragma unroll
    for (int it = 0; it < 2; it++) {
        int c = tid + it * 256;           // 0..511
        int n = c >> 3;
        int d8 = (c & 7) << 3;
        const __half* rp = base + (size_t)n * QKVN + d8;
        __half2 qh[4], kh[4], vh[4];
        *(uint4*)qh = *(const uint4*)(rp);
        *(uint4*)kh = *(const uint4*)(rp + CDIM);
        *(uint4*)vh = *(const uint4*)(rp + 2 * CDIM);
        float q[8], k[8], v[8];
#pragma unroll
        for (int j = 0; j < 4; j++) {
            float2 qf = __half22float2(qh[j]);
            float2 kf = __half22float2(kh[j]);
            float2 vf = __half22float2(vh[j]);
            q[j * 2] = qf.x; q[j * 2 + 1] = qf.y;
            k[j * 2] = kf.x; k[j * 2 + 1] = kf.y;
            v[j * 2] = vf.x; v[j * 2 + 1] = vf.y;
        }
        float sq2 = 0.f, sk2 = 0.f;
#pragma unroll
        for (int j = 0; j < 8; j++) { sq2 += q[j] * q[j]; sk2 += k[j] * k[j]; }
#pragma unroll
        for (int o = 4; o; o >>= 1) {
            sq2 += __shfl_xor_sync(0xffffffffu, sq2, o);
            sk2 += __shfl_xor_sync(0xffffffffu, sk2, o);
        }
        float qi = 1.0f / fmaxf(sqrtf(sq2), 1e-12f);
        float ki = 1.0f / fmaxf(sqrtf(sk2), 1e-12f);
#pragma unroll
        for (int j = 0; j < 8; j++) {
            sqT[(d8 + j) * AP + n] = q[j] * qi;
            skT[(d8 + j) * AP + n] = k[j] * ki;
        }
        *(float4*)(sv + n * AP + d8)     = make_float4(v[0], v[1], v[2], v[3]);
        *(float4*)(sv + n * AP + d8 + 4) = make_float4(v[4], v[5], v[6], v[7]);
    }
    __syncthreads();

    const float scale = expf(fminf(logit_scale[h], 4.605170185988091f));
    const int tx = tid & 15, ty = tid >> 4;
    const int i0 = ty * 4, j0 = tx * 4;

    // S = qn @ kn^T with packed f32x2
    unsigned long long acc2[4][2];
#pragma unroll
    for (int i = 0; i < 4; i++) { acc2[i][0] = 0ull; acc2[i][1] = 0ull; }

    for (int kk = 0; kk < 64; kk++) {
        float4 a4 = *(const float4*)(sqT + kk * AP + i0);
        ulonglong2 bb = *(const ulonglong2*)(skT + kk * AP + j0);
        float a[4] = {a4.x, a4.y, a4.z, a4.w};
#pragma unroll
        for (int i = 0; i < 4; i++) {
            unsigned long long aa = pack2(a[i], a[i]);
            fma2(acc2[i][0], aa, bb.x);
            fma2(acc2[i][1], aa, bb.y);
        }
    }

    float acc[4][4];
#pragma unroll
    for (int i = 0; i < 4; i++) {
        unpack2(acc2[i][0], acc[i][0], acc[i][1]);
        unpack2(acc2[i][1], acc[i][2], acc[i][3]);
    }

    const float* mrow = mask + (size_t)(b & 63) * NTOK * NTOK;
#pragma unroll
    for (int i = 0; i < 4; i++) {
        int I = i0 + i;
        float4 m4 = __ldg((const float4*)(mrow + I * 64 + j0));
        float mm[4] = {m4.x, m4.y, m4.z, m4.w};
#pragma unroll
        for (int j = 0; j < 4; j++) {
            int J = j0 + j;
            int t = ((I >> 3) - (J >> 3) + 7) * 15 + ((I & 7) - (J & 7) + 7);
            acc[i][j] = fmaf(acc[i][j], scale, scpb[t]) + mm[j];
        }
    }

#pragma unroll
    for (int i = 0; i < 4; i++) {
        float m = fmaxf(fmaxf(acc[i][0], acc[i][1]), fmaxf(acc[i][2], acc[i][3]));
#pragma unroll
        for (int o = 8; o; o >>= 1) m = fmaxf(m, __shfl_xor_sync(0xffffffffu, m, o));
        float e0 = __expf(acc[i][0] - m);
        float e1 = __expf(acc[i][1] - m);
        float e2 = __expf(acc[i][2] - m);
        float e3 = __expf(acc[i][3] - m);
        float s = e0 + e1 + e2 + e3;
#pragma unroll
        for (int o = 8; o; o >>= 1) s += __shfl_xor_sync(0xffffffffu, s, o);
        float inv = 1.f / s;
        acc[i][0] = e0 * inv; acc[i][1] = e1 * inv;
        acc[i][2] = e2 * inv; acc[i][3] = e3 * inv;
    }

#pragma unroll
    for (int j = 0; j < 4; j++) {
        *(float4*)(sp + (j0 + j) * AP + i0) =
            make_float4(acc[0][j], acc[1][j], acc[2][j], acc[3][j]);
    }
    __syncthreads();

    // O = P @ V with packed f32x2
    unsigned long long o2[4][2];
#pragma unroll
    for (int i = 0; i < 4; i++) { o2[i][0] = 0ull; o2[i][1] = 0ull; }

    for (int jj = 0; jj < 64; jj++) {
        float4 p4 = *(const float4*)(sp + jj * AP + i0);
        ulonglong2 vv = *(const ulonglong2*)(sv + jj * AP + j0);
        float p[4] = {p4.x, p4.y, p4.z, p4.w};
#pragma unroll
        for (int i = 0; i < 4; i++) {
            unsigned long long pp = pack2(p[i], p[i]);
            fma2(o2[i][0], pp, vv.x);
            fma2(o2[i][1], pp, vv.y);
        }
    }

#pragma unroll
    for (int i = 0; i < 4; i++) {
        float o[4];
        unpack2(o2[i][0], o[0], o[1]);
        unpack2(o2[i][1], o[2], o[3]);
        size_t off = ((size_t)(b * NTOK + i0 + i)) * CDIM + h * HDIM + j0;
        __half h0 = __float2half(o[0]);
        __half h1 = __float2half(o[1]);
        __half h2 = __float2half(o[2]);
        __half h3 = __float2half(o[3]);
        __half l0 = __float2half(o[0] - __half2float(h0));
        __half l1 = __float2half(o[1] - __half2float(h1));
        __half l2 = __float2half(o[2] - __half2float(h2));
        __half l3 = __float2half(o[3] - __half2float(h3));
        __half2* hp = (__half2*)(g_ahi + off);
        __half2* lp = (__half2*)(g_alo + off);
        hp[0] = __halves2half2(h0, h1);
        hp[1] = __halves2half2(h2, h3);
        lp[0] = __halves2half2(l0, l1);
        lp[1] = __halves2half2(l2, l3);
    }
}

// ---------------------------------------------------------------------------
// launch
// ---------------------------------------------------------------------------
extern "C" void kernel_launch(void* const* d_in, const int* in_sizes, int n_in,
                              void* d_out, int out_size) {
    const float* x           = (const float*)d_in[0];
    const float* mask        = (const float*)d_in[1];
    const float* qkv_w       = (const float*)d_in[2];
    const float* q_bias      = (const float*)d_in[3];
    const float* v_bias      = (const float*)d_in[4];
    const float* logit_scale = (const float*)d_in[5];
    const float* cpb_w1      = (const float*)d_in[6];
    const float* cpb_b1      = (const float*)d_in[7];
    const float* cpb_w2      = (const float*)d_in[8];
    const float* proj_w      = (const float*)d_in[9];
    const float* proj_b      = (const float*)d_in[10];
    float* out = (float*)d_out;

    float* bias_p;
    __half *qkvh, *xhi, *xlo, *wh, *ph, *ahi, *alo;
    cudaGetSymbolAddress((void**)&qkvh, g_qkvh);
    cudaGetSymbolAddress((void**)&bias_p, g_bias);
    cudaGetSymbolAddress((void**)&xhi, g_xhi);
    cudaGetSymbolAddress((void**)&xlo, g_xlo);
    cudaGetSymbolAddress((void**)&wh, g_wh);
    cudaGetSymbolAddress((void**)&ph, g_ph);
    cudaGetSymbolAddress((void**)&ahi, g_ahi);
    cudaGetSymbolAddress((void**)&alo, g_alo);

    cudaFuncSetAttribute(gemm2h<true>,  cudaFuncAttributeMaxDynamicSharedMemorySize, GEMM_SMEM);
    cudaFuncSetAttribute(gemm2h<false>, cudaFuncAttributeMaxDynamicSharedMemorySize, GEMM_SMEM);
    cudaFuncSetAttribute(attn_kernel, cudaFuncAttributeMaxDynamicSharedMemorySize, (int)ATTN_SMEM);

    // conversions + tables
    conv_hilo_h<<<8192, 256>>>((const float4*)x, xhi, xlo, MTOT * CDIM / 4);
    conv_h2<<<1024, 256>>>((const float4*)qkv_w, wh, QKVN * CDIM / 4,
                           (const float4*)proj_w, ph, CDIM * CDIM / 4);
    cpb_bias_kernel<<<249, 64>>>(cpb_w1, cpb_b1, cpb_w2, q_bias, v_bias);

    // QKV projection -> fp16 qkv: grid (12, 512)
    {
        dim3 grid(QKVN / 128, MTOT / 128);
        gemm2h<true><<<grid, 256, GEMM_SMEM>>>(xhi, xlo, wh, nullptr, qkvh, bias_p, QKVN);
    }

    // fused attention
    {
        dim3 grid(BATCH, NHEAD);
        attn_kernel<<<grid, 256, ATTN_SMEM>>>(mask, logit_scale);
    }

    // output projection -> d_out fp32: grid (4, 512)
    {
        dim3 grid(CDIM / 128, MTOT / 128);
        gemm2h<false><<<grid, 256, GEMM_SMEM>>>(ahi, alo, ph, out, nullptr, proj_b, CDIM);
    }
}

// round 6
// speedup vs baseline: 5.0742x; 1.1766x over previous
#include <cuda_runtime.h>
#include <cuda_fp16.h>
#include <cstdint>

// ---------------------------------------------------------------------------
// Problem constants
// ---------------------------------------------------------------------------
#define BATCH 1024
#define NTOK  64
#define CDIM  512
#define NHEAD 8
#define HDIM  64
#define MTOT  (BATCH * NTOK)      // 65536
#define QKVN  (3 * CDIM)          // 1536

// ---------------------------------------------------------------------------
// Device-global scratch (allocation-free)
// ---------------------------------------------------------------------------
__device__ __align__(16) __half  g_qkvh[(size_t)MTOT * QKVN];   // fp16 qkv
__device__ __align__(16) __half  g_xhi[(size_t)MTOT * CDIM];
__device__ __align__(16) __half  g_xlo[(size_t)MTOT * CDIM];
__device__ __align__(16) __half  g_wh[QKVN * CDIM];
__device__ __align__(16) __half  g_ph[CDIM * CDIM];
__device__ __align__(16) __half  g_ahi[(size_t)MTOT * CDIM];
__device__ __align__(16) __half  g_alo[(size_t)MTOT * CDIM];
__device__ __align__(16) float   g_bias[QKVN];
__device__ __align__(16) float   g_cpb[225 * 8];

// ---------------------------------------------------------------------------
// PTX helpers
// ---------------------------------------------------------------------------
__device__ __forceinline__ uint32_t s2u(const void* p) {
    return (uint32_t)__cvta_generic_to_shared(p);
}
__device__ __forceinline__ void cpa16(uint32_t saddr, const void* g) {
    asm volatile("cp.async.cg.shared.global [%0], [%1], 16;" :: "r"(saddr), "l"(g) : "memory");
}
__device__ __forceinline__ void cpa_commit() {
    asm volatile("cp.async.commit_group;" ::: "memory");
}
__device__ __forceinline__ void cpa_wait1() {
    asm volatile("cp.async.wait_group 1;" ::: "memory");
}
__device__ __forceinline__ void cpa_wait0() {
    asm volatile("cp.async.wait_group 0;" ::: "memory");
}
#define LDSM4(r, addr) \
    asm volatile("ldmatrix.sync.aligned.m8n8.x4.shared.b16 {%0,%1,%2,%3}, [%4];" \
        : "=r"((r)[0]), "=r"((r)[1]), "=r"((r)[2]), "=r"((r)[3]) : "r"(addr))
#define MMAH16816(c, a, b0, b1) \
    asm volatile("mma.sync.aligned.m16n8k16.row.col.f32.f16.f16.f32 " \
        "{%0,%1,%2,%3},{%4,%5,%6,%7},{%8,%9},{%0,%1,%2,%3};" \
        : "+f"((c)[0]), "+f"((c)[1]), "+f"((c)[2]), "+f"((c)[3]) \
        : "r"((a)[0]), "r"((a)[1]), "r"((a)[2]), "r"((a)[3]), "r"(b0), "r"(b1))

// f32x2 packed fp32 math (B300: 2x fp32 FMA throughput)
__device__ __forceinline__ unsigned long long pack2(float x, float y) {
    unsigned long long r;
    asm("mov.b64 %0, {%1, %2};" : "=l"(r) : "r"(__float_as_uint(x)), "r"(__float_as_uint(y)));
    return r;
}
__device__ __forceinline__ void fma2(unsigned long long& d, unsigned long long a, unsigned long long b) {
    asm("fma.rn.f32x2 %0, %1, %2, %0;" : "+l"(d) : "l"(a), "l"(b));
}
__device__ __forceinline__ void unpack2(unsigned long long v, float& x, float& y) {
    unsigned int lo, hi;
    asm("mov.b64 {%0, %1}, %2;" : "=r"(lo), "=r"(hi) : "l"(v));
    x = __uint_as_float(lo); y = __uint_as_float(hi);
}

// ---------------------------------------------------------------------------
// fp32 -> fp16 hi/lo split (x)
// ---------------------------------------------------------------------------
__global__ void conv_hilo_h(const float4* __restrict__ in, __half* __restrict__ hi,
                            __half* __restrict__ lo, int n4) {
    int stride = gridDim.x * blockDim.x;
    for (int i = blockIdx.x * blockDim.x + threadIdx.x; i < n4; i += stride) {
        float4 v = in[i];
        __half h0 = __float2half(v.x), h1 = __float2half(v.y);
        __half h2 = __float2half(v.z), h3 = __float2half(v.w);
        __half l0 = __float2half(v.x - __half2float(h0));
        __half l1 = __float2half(v.y - __half2float(h1));
        __half l2 = __float2half(v.z - __half2float(h2));
        __half l3 = __float2half(v.w - __half2float(h3));
        __half2* hp = (__half2*)(hi + (size_t)i * 4);
        __half2* lp = (__half2*)(lo + (size_t)i * 4);
        hp[0] = __halves2half2(h0, h1);
        hp[1] = __halves2half2(h2, h3);
        lp[0] = __halves2half2(l0, l1);
        lp[1] = __halves2half2(l2, l3);
    }
}

// both weight conversions in one launch
__global__ void conv_h2(const float4* __restrict__ w, __half* __restrict__ wh, int n4w,
                        const float4* __restrict__ p, __half* __restrict__ ph, int n4p) {
    int stride = gridDim.x * blockDim.x;
    int total = n4w + n4p;
    for (int i = blockIdx.x * blockDim.x + threadIdx.x; i < total; i += stride) {
        const float4* src; __half* dst; int idx;
        if (i < n4w) { src = w; dst = wh; idx = i; }
        else         { src = p; dst = ph; idx = i - n4w; }
        float4 v = src[idx];
        __half2* op = (__half2*)(dst + (size_t)idx * 4);
        op[0] = __halves2half2(__float2half(v.x), __float2half(v.y));
        op[1] = __halves2half2(__float2half(v.z), __float2half(v.w));
    }
}

// ---------------------------------------------------------------------------
// CPB MLP + bias build in one launch
// ---------------------------------------------------------------------------
__device__ __forceinline__ float signed_log_coord(int d) {
    float g = (float)d / 7.0f * 8.0f;
    float s = (g > 0.f) ? 1.f : ((g < 0.f) ? -1.f : 0.f);
    return s * log2f(fabsf(g) + 1.0f) / log2f(9.0f);
}
__global__ void cpb_bias_kernel(const float* __restrict__ w1, const float* __restrict__ b1,
                                const float* __restrict__ w2,
                                const float* __restrict__ qb, const float* __restrict__ vb) {
    int t = blockIdx.x;
    if (t >= 225) {
        int i = (t - 225) * 64 + threadIdx.x;
        if (threadIdx.x < 64 && i < QKVN)
            g_bias[i] = (i < 512) ? qb[i] : ((i < 1024) ? 0.f : vb[i - 1024]);
        return;
    }
    float c0 = signed_log_coord(t / 15 - 7);
    float c1 = signed_log_coord(t % 15 - 7);
    __shared__ float red[64][8];
    float p[8];
#pragma unroll
    for (int h = 0; h < 8; h++) p[h] = 0.f;
    for (int j = threadIdx.x; j < 512; j += 64) {
        float hx = fmaf(c0, w1[2 * j], fmaf(c1, w1[2 * j + 1], b1[j]));
        hx = fmaxf(hx, 0.f);
#pragma unroll
        for (int h = 0; h < 8; h++) p[h] += hx * w2[h * 512 + j];
    }
#pragma unroll
    for (int h = 0; h < 8; h++) red[threadIdx.x][h] = p[h];
    __syncthreads();
    if (threadIdx.x < 8) {
        float s = 0.f;
#pragma unroll
        for (int i = 0; i < 64; i++) s += red[i][threadIdx.x];
        g_cpb[t * 8 + threadIdx.x] = 16.f / (1.f + expf(-s));
    }
}

// ---------------------------------------------------------------------------
// HMMA GEMM (fp16 2-pass): C[M,N] = (Ah+Al)[M,512] @ B[N,512]^T + bias[n]
// Tile 128x128x32, 8 warps (2x4), 3-stage cp.async. 2 CTAs/SM resident.
// ---------------------------------------------------------------------------
#define LDT 80
#define TILE_BYTES (128 * LDT)
#define A_HI 0
#define A_LO TILE_BYTES
#define B_OF (2 * TILE_BYTES)
#define SS (3 * TILE_BYTES)          // 30720 per stage
#define GEMM_SMEM (3 * SS)           // 92160

__device__ __forceinline__ void load_stage(
    uint32_t sbase, int kt,
    const __half* __restrict__ Ah, const __half* __restrict__ Al,
    const __half* __restrict__ B,
    int m0, int n0, int tid) {
    const int k0 = kt * 32;
#pragma unroll
    for (int i = 0; i < 2; i++) {
        int id = tid + i * 256;
        int r = id >> 2, c = id & 3;
        uint32_t so = (uint32_t)(r * LDT + c * 16);
        size_t ga = (size_t)(m0 + r) * CDIM + k0 + c * 8;
        size_t gb = (size_t)(n0 + r) * CDIM + k0 + c * 8;
        cpa16(sbase + A_HI + so, Ah + ga);
        cpa16(sbase + A_LO + so, Al + ga);
        cpa16(sbase + B_OF + so, B + gb);
    }
    cpa_commit();
}

template <bool HALF_OUT>
__global__ void __launch_bounds__(256, 2)
gemm2h(const __half* __restrict__ Ah, const __half* __restrict__ Al,
       const __half* __restrict__ B,
       float* __restrict__ Cf, __half* __restrict__ Ch,
       const float* __restrict__ bias, int ldc) {
    extern __shared__ char dsm[];
    const uint32_t smb = s2u(dsm);

    const int tid = threadIdx.x;
    const int wid = tid >> 5;
    const int lane = tid & 31;
    const int wm = wid >> 2;
    const int wn = wid & 3;
    const int m0 = blockIdx.y * 128;
    const int n0 = blockIdx.x * 128;

    float acc[16][4];
#pragma unroll
    for (int t = 0; t < 16; t++)
#pragma unroll
        for (int e = 0; e < 4; e++) acc[t][e] = 0.f;

    load_stage(smb + 0 * SS, 0, Ah, Al, B, m0, n0, tid);
    load_stage(smb + 1 * SS, 1, Ah, Al, B, m0, n0, tid);

    const uint32_t a_row = (uint32_t)((wm * 64 + (lane & 15)) * LDT + (lane >> 4) * 16);
    const uint32_t b_row = (uint32_t)((wn * 32 + (lane & 7) + ((lane >> 4) << 3)) * LDT
                                      + ((lane >> 3) & 1) * 16);

    const int NK = CDIM / 32;  // 16
    for (int kt = 0; kt < NK; kt++) {
        if (kt + 2 < NK) cpa_wait1(); else cpa_wait0();
        __syncthreads();
        if (kt + 2 < NK)
            load_stage(smb + (uint32_t)((kt + 2) % 3) * SS, kt + 2, Ah, Al, B, m0, n0, tid);

        const uint32_t st = smb + (uint32_t)(kt % 3) * SS;
#pragma unroll
        for (int ks = 0; ks < 2; ks++) {
            const uint32_t koff = (uint32_t)(ks * 32);
            uint32_t bh[2][4];
#pragma unroll
            for (int nf = 0; nf < 2; nf++) {
                uint32_t bd = st + b_row + (uint32_t)(nf * 16 * LDT) + koff;
                LDSM4(bh[nf], bd + B_OF);
            }
            // per-i fragment loads keep register liveness low (2 CTAs/SM)
#pragma unroll
            for (int i = 0; i < 4; i++) {
                uint32_t ah[4], al[4];
                uint32_t ad = st + a_row + (uint32_t)(i * 16 * LDT) + koff;
                LDSM4(ah, ad + A_HI);
                LDSM4(al, ad + A_LO);
#pragma unroll
                for (int j = 0; j < 4; j++) {
                    float* c = acc[i * 4 + j];
                    int nf = j >> 1, sb = (j & 1) * 2;
                    MMAH16816(c, ah, bh[nf][sb], bh[nf][sb + 1]);
                    MMAH16816(c, al, bh[nf][sb], bh[nf][sb + 1]);
                }
            }
        }
    }

#pragma unroll
    for (int i = 0; i < 4; i++) {
#pragma unroll
        for (int j = 0; j < 4; j++) {
            const float* c = acc[i * 4 + j];
            int row = m0 + wm * 64 + i * 16 + (lane >> 2);
            int col = n0 + wn * 32 + j * 8 + (lane & 3) * 2;
            float2 b2 = __ldg((const float2*)(bias + col));
            if (HALF_OUT) {
                __half2 v0 = __floats2half2_rn(c[0] + b2.x, c[1] + b2.y);
                __half2 v1 = __floats2half2_rn(c[2] + b2.x, c[3] + b2.y);
                *(__half2*)(Ch + (size_t)row * ldc + col) = v0;
                *(__half2*)(Ch + (size_t)(row + 8) * ldc + col) = v1;
            } else {
                float2 v0 = make_float2(c[0] + b2.x, c[1] + b2.y);
                float2 v1 = make_float2(c[2] + b2.x, c[3] + b2.y);
                *(float2*)(Cf + (size_t)row * ldc + col) = v0;
                *(float2*)(Cf + (size_t)(row + 8) * ldc + col) = v1;
            }
        }
    }
}

// ---------------------------------------------------------------------------
// Fused attention. grid=(1024,8), 256 threads. fp16 qkv in, f32x2 math.
// ---------------------------------------------------------------------------
#define AP 68
#define ATTN_SMEM ((4 * 64 * AP + 225) * sizeof(float))

__global__ void __launch_bounds__(256)
attn_kernel(const float* __restrict__ mask, const float* __restrict__ logit_scale) {
    const int b = blockIdx.x;
    const int h = blockIdx.y;
    extern __shared__ float smf[];
    float* sqT = smf;                 // [64][AP] q transposed [d][n]
    float* skT = smf + 64 * AP;
    float* sv  = smf + 2 * 64 * AP;   // [n][d]
    float* sp  = smf + 3 * 64 * AP;   // P transposed [j][i]
    float* scpb = smf + 4 * 64 * AP;

    const int tid = threadIdx.x;
    if (tid < 225) scpb[tid] = g_cpb[tid * 8 + h];

    const __half* base = g_qkvh + (size_t)b * NTOK * QKVN + h * HDIM;
#pragma unroll
    for (int it = 0; it < 2; it++) {
        int c = tid + it * 256;           // 0..511
        int n = c >> 3;
        int d8 = (c & 7) << 3;
        const __half* rp = base + (size_t)n * QKVN + d8;
        __half2 qh[4], kh[4], vh[4];
        *(uint4*)qh = *(const uint4*)(rp);
        *(uint4*)kh = *(const uint4*)(rp + CDIM);
        *(uint4*)vh = *(const uint4*)(rp + 2 * CDIM);
        float q[8], k[8], v[8];
#pragma unroll
        for (int j = 0; j < 4; j++) {
            float2 qf = __half22float2(qh[j]);
            float2 kf = __half22float2(kh[j]);
            float2 vf = __half22float2(vh[j]);
            q[j * 2] = qf.x; q[j * 2 + 1] = qf.y;
            k[j * 2] = kf.x; k[j * 2 + 1] = kf.y;
            v[j * 2] = vf.x; v[j * 2 + 1] = vf.y;
        }
        float sq2 = 0.f, sk2 = 0.f;
#pragma unroll
        for (int j = 0; j < 8; j++) { sq2 += q[j] * q[j]; sk2 += k[j] * k[j]; }
#pragma unroll
        for (int o = 4; o; o >>= 1) {
            sq2 += __shfl_xor_sync(0xffffffffu, sq2, o);
            sk2 += __shfl_xor_sync(0xffffffffu, sk2, o);
        }
        float qi = 1.0f / fmaxf(sqrtf(sq2), 1e-12f);
        float ki = 1.0f / fmaxf(sqrtf(sk2), 1e-12f);
#pragma unroll
        for (int j = 0; j < 8; j++) {
            sqT[(d8 + j) * AP + n] = q[j] * qi;
            skT[(d8 + j) * AP + n] = k[j] * ki;
        }
        *(float4*)(sv + n * AP + d8)     = make_float4(v[0], v[1], v[2], v[3]);
        *(float4*)(sv + n * AP + d8 + 4) = make_float4(v[4], v[5], v[6], v[7]);
    }
    __syncthreads();

    const float scale = expf(fminf(logit_scale[h], 4.605170185988091f));
    const int tx = tid & 15, ty = tid >> 4;
    const int i0 = ty * 4, j0 = tx * 4;

    // S = qn @ kn^T with packed f32x2
    unsigned long long acc2[4][2];
#pragma unroll
    for (int i = 0; i < 4; i++) { acc2[i][0] = 0ull; acc2[i][1] = 0ull; }

    for (int kk = 0; kk < 64; kk++) {
        float4 a4 = *(const float4*)(sqT + kk * AP + i0);
        ulonglong2 bb = *(const ulonglong2*)(skT + kk * AP + j0);
        float a[4] = {a4.x, a4.y, a4.z, a4.w};
#pragma unroll
        for (int i = 0; i < 4; i++) {
            unsigned long long aa = pack2(a[i], a[i]);
            fma2(acc2[i][0], aa, bb.x);
            fma2(acc2[i][1], aa, bb.y);
        }
    }

    float acc[4][4];
#pragma unroll
    for (int i = 0; i < 4; i++) {
        unpack2(acc2[i][0], acc[i][0], acc[i][1]);
        unpack2(acc2[i][1], acc[i][2], acc[i][3]);
    }

    const float* mrow = mask + (size_t)(b & 63) * NTOK * NTOK;
#pragma unroll
    for (int i = 0; i < 4; i++) {
        int I = i0 + i;
        float4 m4 = __ldg((const float4*)(mrow + I * 64 + j0));
        float mm[4] = {m4.x, m4.y, m4.z, m4.w};
#pragma unroll
        for (int j = 0; j < 4; j++) {
            int J = j0 + j;
            int t = ((I >> 3) - (J >> 3) + 7) * 15 + ((I & 7) - (J & 7) + 7);
            acc[i][j] = fmaf(acc[i][j], scale, scpb[t]) + mm[j];
        }
    }

#pragma unroll
    for (int i = 0; i < 4; i++) {
        float m = fmaxf(fmaxf(acc[i][0], acc[i][1]), fmaxf(acc[i][2], acc[i][3]));
#pragma unroll
        for (int o = 8; o; o >>= 1) m = fmaxf(m, __shfl_xor_sync(0xffffffffu, m, o));
        float e0 = __expf(acc[i][0] - m);
        float e1 = __expf(acc[i][1] - m);
        float e2 = __expf(acc[i][2] - m);
        float e3 = __expf(acc[i][3] - m);
        float s = e0 + e1 + e2 + e3;
#pragma unroll
        for (int o = 8; o; o >>= 1) s += __shfl_xor_sync(0xffffffffu, s, o);
        float inv = 1.f / s;
        acc[i][0] = e0 * inv; acc[i][1] = e1 * inv;
        acc[i][2] = e2 * inv; acc[i][3] = e3 * inv;
    }

#pragma unroll
    for (int j = 0; j < 4; j++) {
        *(float4*)(sp + (j0 + j) * AP + i0) =
            make_float4(acc[0][j], acc[1][j], acc[2][j], acc[3][j]);
    }
    __syncthreads();

    // O = P @ V with packed f32x2
    unsigned long long o2[4][2];
#pragma unroll
    for (int i = 0; i < 4; i++) { o2[i][0] = 0ull; o2[i][1] = 0ull; }

    for (int jj = 0; jj < 64; jj++) {
        float4 p4 = *(const float4*)(sp + jj * AP + i0);
        ulonglong2 vv = *(const ulonglong2*)(sv + jj * AP + j0);
        float p[4] = {p4.x, p4.y, p4.z, p4.w};
#pragma unroll
        for (int i = 0; i < 4; i++) {
            unsigned long long pp = pack2(p[i], p[i]);
            fma2(o2[i][0], pp, vv.x);
            fma2(o2[i][1], pp, vv.y);
        }
    }

#pragma unroll
    for (int i = 0; i < 4; i++) {
        float o[4];
        unpack2(o2[i][0], o[0], o[1]);
        unpack2(o2[i][1], o[2], o[3]);
        size_t off = ((size_t)(b * NTOK + i0 + i)) * CDIM + h * HDIM + j0;
        __half h0 = __float2half(o[0]);
        __half h1 = __float2half(o[1]);
        __half h2 = __float2half(o[2]);
        __half h3 = __float2half(o[3]);
        __half l0 = __float2half(o[0] - __half2float(h0));
        __half l1 = __float2half(o[1] - __half2float(h1));
        __half l2 = __float2half(o[2] - __half2float(h2));
        __half l3 = __float2half(o[3] - __half2float(h3));
        __half2* hp = (__half2*)(g_ahi + off);
        __half2* lp = (__half2*)(g_alo + off);
        hp[0] = __halves2half2(h0, h1);
        hp[1] = __halves2half2(h2, h3);
        lp[0] = __halves2half2(l0, l1);
        lp[1] = __halves2half2(l2, l3);
    }
}

// ---------------------------------------------------------------------------
// launch
// ---------------------------------------------------------------------------
extern "C" void kernel_launch(void* const* d_in, const int* in_sizes, int n_in,
                              void* d_out, int out_size) {
    const float* x           = (const float*)d_in[0];
    const float* mask        = (const float*)d_in[1];
    const float* qkv_w       = (const float*)d_in[2];
    const float* q_bias      = (const float*)d_in[3];
    const float* v_bias      = (const float*)d_in[4];
    const float* logit_scale = (const float*)d_in[5];
    const float* cpb_w1      = (const float*)d_in[6];
    const float* cpb_b1      = (const float*)d_in[7];
    const float* cpb_w2      = (const float*)d_in[8];
    const float* proj_w      = (const float*)d_in[9];
    const float* proj_b      = (const float*)d_in[10];
    float* out = (float*)d_out;

    float* bias_p;
    __half *qkvh, *xhi, *xlo, *wh, *ph, *ahi, *alo;
    cudaGetSymbolAddress((void**)&qkvh, g_qkvh);
    cudaGetSymbolAddress((void**)&bias_p, g_bias);
    cudaGetSymbolAddress((void**)&xhi, g_xhi);
    cudaGetSymbolAddress((void**)&xlo, g_xlo);
    cudaGetSymbolAddress((void**)&wh, g_wh);
    cudaGetSymbolAddress((void**)&ph, g_ph);
    cudaGetSymbolAddress((void**)&ahi, g_ahi);
    cudaGetSymbolAddress((void**)&alo, g_alo);

    cudaFuncSetAttribute(gemm2h<true>,  cudaFuncAttributeMaxDynamicSharedMemorySize, GEMM_SMEM);
    cudaFuncSetAttribute(gemm2h<false>, cudaFuncAttributeMaxDynamicSharedMemorySize, GEMM_SMEM);
    cudaFuncSetAttribute(attn_kernel, cudaFuncAttributeMaxDynamicSharedMemorySize, (int)ATTN_SMEM);

    // conversions + tables
    conv_hilo_h<<<8192, 256>>>((const float4*)x, xhi, xlo, MTOT * CDIM / 4);
    conv_h2<<<1024, 256>>>((const float4*)qkv_w, wh, QKVN * CDIM / 4,
                           (const float4*)proj_w, ph, CDIM * CDIM / 4);
    cpb_bias_kernel<<<249, 64>>>(cpb_w1, cpb_b1, cpb_w2, q_bias, v_bias);

    // QKV projection -> fp16 qkv: grid (12, 512)
    {
        dim3 grid(QKVN / 128, MTOT / 128);
        gemm2h<true><<<grid, 256, GEMM_SMEM>>>(xhi, xlo, wh, nullptr, qkvh, bias_p, QKVN);
    }

    // fused attention
    {
        dim3 grid(BATCH, NHEAD);
        attn_kernel<<<grid, 256, ATTN_SMEM>>>(mask, logit_scale);
    }

    // output projection -> d_out fp32: grid (4, 512)
    {
        dim3 grid(CDIM / 128, MTOT / 128);
        gemm2h<false><<<grid, 256, GEMM_SMEM>>>(ahi, alo, ph, out, nullptr, proj_b, CDIM);
    }
}

// round 7
// speedup vs baseline: 5.5246x; 1.0888x over previous
#include <cuda_runtime.h>
#include <cuda_fp16.h>
#include <cstdint>

// ---------------------------------------------------------------------------
// Problem constants
// ---------------------------------------------------------------------------
#define BATCH 1024
#define NTOK  64
#define CDIM  512
#define NHEAD 8
#define HDIM  64
#define MTOT  (BATCH * NTOK)      // 65536
#define QKVN  (3 * CDIM)          // 1536

// ---------------------------------------------------------------------------
// Device-global scratch (allocation-free)
// ---------------------------------------------------------------------------
__device__ __align__(16) __half  g_qkvh[(size_t)MTOT * QKVN];   // fp16 qkv
__device__ __align__(16) __half  g_xhi[(size_t)MTOT * CDIM];
__device__ __align__(16) __half  g_xlo[(size_t)MTOT * CDIM];
__device__ __align__(16) __half  g_wh[QKVN * CDIM];
__device__ __align__(16) __half  g_ph[CDIM * CDIM];
__device__ __align__(16) __half  g_ahi[(size_t)MTOT * CDIM];
__device__ __align__(16) __half  g_alo[(size_t)MTOT * CDIM];
__device__ __align__(16) float   g_bias[QKVN];
__device__ __align__(16) float   g_cpb[225 * 8];

// ---------------------------------------------------------------------------
// PTX helpers
// ---------------------------------------------------------------------------
__device__ __forceinline__ uint32_t s2u(const void* p) {
    return (uint32_t)__cvta_generic_to_shared(p);
}
__device__ __forceinline__ void cpa16(uint32_t saddr, const void* g) {
    asm volatile("cp.async.cg.shared.global [%0], [%1], 16;" :: "r"(saddr), "l"(g) : "memory");
}
__device__ __forceinline__ void cpa_commit() {
    asm volatile("cp.async.commit_group;" ::: "memory");
}
__device__ __forceinline__ void cpa_wait0() {
    asm volatile("cp.async.wait_group 0;" ::: "memory");
}
#define LDSM4(r, addr) \
    asm volatile("ldmatrix.sync.aligned.m8n8.x4.shared.b16 {%0,%1,%2,%3}, [%4];" \
        : "=r"((r)[0]), "=r"((r)[1]), "=r"((r)[2]), "=r"((r)[3]) : "r"(addr))
#define MMAH16816(c, a, b0, b1) \
    asm volatile("mma.sync.aligned.m16n8k16.row.col.f32.f16.f16.f32 " \
        "{%0,%1,%2,%3},{%4,%5,%6,%7},{%8,%9},{%0,%1,%2,%3};" \
        : "+f"((c)[0]), "+f"((c)[1]), "+f"((c)[2]), "+f"((c)[3]) \
        : "r"((a)[0]), "r"((a)[1]), "r"((a)[2]), "r"((a)[3]), "r"(b0), "r"(b1))

// f32x2 packed fp32 math (B300: 2x fp32 FMA throughput)
__device__ __forceinline__ unsigned long long pack2(float x, float y) {
    unsigned long long r;
    asm("mov.b64 %0, {%1, %2};" : "=l"(r) : "r"(__float_as_uint(x)), "r"(__float_as_uint(y)));
    return r;
}
__device__ __forceinline__ void fma2(unsigned long long& d, unsigned long long a, unsigned long long b) {
    asm("fma.rn.f32x2 %0, %1, %2, %0;" : "+l"(d) : "l"(a), "l"(b));
}
__device__ __forceinline__ void unpack2(unsigned long long v, float& x, float& y) {
    unsigned int lo, hi;
    asm("mov.b64 {%0, %1}, %2;" : "=r"(lo), "=r"(hi) : "l"(v));
    x = __uint_as_float(lo); y = __uint_as_float(hi);
}

// ---------------------------------------------------------------------------
// fp32 -> fp16 hi/lo split (x)
// ---------------------------------------------------------------------------
__global__ void conv_hilo_h(const float4* __restrict__ in, __half* __restrict__ hi,
                            __half* __restrict__ lo, int n4) {
    int stride = gridDim.x * blockDim.x;
    for (int i = blockIdx.x * blockDim.x + threadIdx.x; i < n4; i += stride) {
        float4 v = in[i];
        __half h0 = __float2half(v.x), h1 = __float2half(v.y);
        __half h2 = __float2half(v.z), h3 = __float2half(v.w);
        __half l0 = __float2half(v.x - __half2float(h0));
        __half l1 = __float2half(v.y - __half2float(h1));
        __half l2 = __float2half(v.z - __half2float(h2));
        __half l3 = __float2half(v.w - __half2float(h3));
        __half2* hp = (__half2*)(hi + (size_t)i * 4);
        __half2* lp = (__half2*)(lo + (size_t)i * 4);
        hp[0] = __halves2half2(h0, h1);
        hp[1] = __halves2half2(h2, h3);
        lp[0] = __halves2half2(l0, l1);
        lp[1] = __halves2half2(l2, l3);
    }
}

// both weight conversions in one launch
__global__ void conv_h2(const float4* __restrict__ w, __half* __restrict__ wh, int n4w,
                        const float4* __restrict__ p, __half* __restrict__ ph, int n4p) {
    int stride = gridDim.x * blockDim.x;
    int total = n4w + n4p;
    for (int i = blockIdx.x * blockDim.x + threadIdx.x; i < total; i += stride) {
        const float4* src; __half* dst; int idx;
        if (i < n4w) { src = w; dst = wh; idx = i; }
        else         { src = p; dst = ph; idx = i - n4w; }
        float4 v = src[idx];
        __half2* op = (__half2*)(dst + (size_t)idx * 4);
        op[0] = __halves2half2(__float2half(v.x), __float2half(v.y));
        op[1] = __halves2half2(__float2half(v.z), __float2half(v.w));
    }
}

// ---------------------------------------------------------------------------
// CPB MLP + bias build in one launch
// ---------------------------------------------------------------------------
__device__ __forceinline__ float signed_log_coord(int d) {
    float g = (float)d / 7.0f * 8.0f;
    float s = (g > 0.f) ? 1.f : ((g < 0.f) ? -1.f : 0.f);
    return s * log2f(fabsf(g) + 1.0f) / log2f(9.0f);
}
__global__ void cpb_bias_kernel(const float* __restrict__ w1, const float* __restrict__ b1,
                                const float* __restrict__ w2,
                                const float* __restrict__ qb, const float* __restrict__ vb) {
    int t = blockIdx.x;
    if (t >= 225) {
        int i = (t - 225) * 64 + threadIdx.x;
        if (threadIdx.x < 64 && i < QKVN)
            g_bias[i] = (i < 512) ? qb[i] : ((i < 1024) ? 0.f : vb[i - 1024]);
        return;
    }
    float c0 = signed_log_coord(t / 15 - 7);
    float c1 = signed_log_coord(t % 15 - 7);
    __shared__ float red[64][8];
    float p[8];
#pragma unroll
    for (int h = 0; h < 8; h++) p[h] = 0.f;
    for (int j = threadIdx.x; j < 512; j += 64) {
        float hx = fmaf(c0, w1[2 * j], fmaf(c1, w1[2 * j + 1], b1[j]));
        hx = fmaxf(hx, 0.f);
#pragma unroll
        for (int h = 0; h < 8; h++) p[h] += hx * w2[h * 512 + j];
    }
#pragma unroll
    for (int h = 0; h < 8; h++) red[threadIdx.x][h] = p[h];
    __syncthreads();
    if (threadIdx.x < 8) {
        float s = 0.f;
#pragma unroll
        for (int i = 0; i < 64; i++) s += red[i][threadIdx.x];
        g_cpb[t * 8 + threadIdx.x] = 16.f / (1.f + expf(-s));
    }
}

// ---------------------------------------------------------------------------
// HMMA GEMM (fp16 2-pass): C[M,N] = (Ah+Al)[M,512] @ B[N,512]^T + bias[n]
// Tile 128x128x64, 8 warps (2x4), 2-stage cp.async, 2 CTAs/SM.
// ---------------------------------------------------------------------------
#define LDT 144                      // 128 B data + 16 pad per row
#define TILE_BYTES (128 * LDT)       // 18432
#define A_HI 0
#define A_LO TILE_BYTES
#define B_OF (2 * TILE_BYTES)
#define SS (3 * TILE_BYTES)          // 55296 per stage
#define GEMM_SMEM (2 * SS)           // 110592

__device__ __forceinline__ void load_stage(
    uint32_t sbase, int kt,
    const __half* __restrict__ Ah, const __half* __restrict__ Al,
    const __half* __restrict__ B,
    int m0, int n0, int tid) {
    const int k0 = kt * 64;
#pragma unroll
    for (int i = 0; i < 4; i++) {
        int id = tid + i * 256;          // 0..1023 chunk index per tile
        int r = id >> 3, c = id & 7;
        uint32_t so = (uint32_t)(r * LDT + c * 16);
        size_t ga = (size_t)(m0 + r) * CDIM + k0 + c * 8;
        size_t gb = (size_t)(n0 + r) * CDIM + k0 + c * 8;
        cpa16(sbase + A_HI + so, Ah + ga);
        cpa16(sbase + A_LO + so, Al + ga);
        cpa16(sbase + B_OF + so, B + gb);
    }
    cpa_commit();
}

template <bool HALF_OUT>
__global__ void __launch_bounds__(256, 2)
gemm2h(const __half* __restrict__ Ah, const __half* __restrict__ Al,
       const __half* __restrict__ B,
       float* __restrict__ Cf, __half* __restrict__ Ch,
       const float* __restrict__ bias, int ldc) {
    extern __shared__ char dsm[];
    const uint32_t smb = s2u(dsm);

    const int tid = threadIdx.x;
    const int wid = tid >> 5;
    const int lane = tid & 31;
    const int wm = wid >> 2;
    const int wn = wid & 3;
    const int m0 = blockIdx.y * 128;
    const int n0 = blockIdx.x * 128;

    float acc[16][4];
#pragma unroll
    for (int t = 0; t < 16; t++)
#pragma unroll
        for (int e = 0; e < 4; e++) acc[t][e] = 0.f;

    load_stage(smb, 0, Ah, Al, B, m0, n0, tid);

    const uint32_t a_row = (uint32_t)((wm * 64 + (lane & 15)) * LDT + (lane >> 4) * 16);
    const uint32_t b_row = (uint32_t)((wn * 32 + (lane & 7) + ((lane >> 4) << 3)) * LDT
                                      + ((lane >> 3) & 1) * 16);

    const int NK = CDIM / 64;  // 8
    for (int kt = 0; kt < NK; kt++) {
        cpa_wait0();
        __syncthreads();
        if (kt + 1 < NK)
            load_stage(smb + (uint32_t)((kt + 1) & 1) * SS, kt + 1, Ah, Al, B, m0, n0, tid);

        const uint32_t st = smb + (uint32_t)(kt & 1) * SS;
#pragma unroll
        for (int ks = 0; ks < 4; ks++) {
            const uint32_t koff = (uint32_t)(ks * 32);
            uint32_t bh[2][4];
#pragma unroll
            for (int nf = 0; nf < 2; nf++) {
                uint32_t bd = st + b_row + (uint32_t)(nf * 16 * LDT) + koff;
                LDSM4(bh[nf], bd + B_OF);
            }
#pragma unroll
            for (int i = 0; i < 4; i++) {
                uint32_t ah[4], al[4];
                uint32_t ad = st + a_row + (uint32_t)(i * 16 * LDT) + koff;
                LDSM4(ah, ad + A_HI);
                LDSM4(al, ad + A_LO);
#pragma unroll
                for (int j = 0; j < 4; j++) {
                    float* c = acc[i * 4 + j];
                    int nf = j >> 1, sb = (j & 1) * 2;
                    MMAH16816(c, ah, bh[nf][sb], bh[nf][sb + 1]);
                    MMAH16816(c, al, bh[nf][sb], bh[nf][sb + 1]);
                }
            }
        }
    }

#pragma unroll
    for (int i = 0; i < 4; i++) {
#pragma unroll
        for (int j = 0; j < 4; j++) {
            const float* c = acc[i * 4 + j];
            int row = m0 + wm * 64 + i * 16 + (lane >> 2);
            int col = n0 + wn * 32 + j * 8 + (lane & 3) * 2;
            float2 b2 = __ldg((const float2*)(bias + col));
            if (HALF_OUT) {
                __half2 v0 = __floats2half2_rn(c[0] + b2.x, c[1] + b2.y);
                __half2 v1 = __floats2half2_rn(c[2] + b2.x, c[3] + b2.y);
                *(__half2*)(Ch + (size_t)row * ldc + col) = v0;
                *(__half2*)(Ch + (size_t)(row + 8) * ldc + col) = v1;
            } else {
                float2 v0 = make_float2(c[0] + b2.x, c[1] + b2.y);
                float2 v1 = make_float2(c[2] + b2.x, c[3] + b2.y);
                *(float2*)(Cf + (size_t)row * ldc + col) = v0;
                *(float2*)(Cf + (size_t)(row + 8) * ldc + col) = v1;
            }
        }
    }
}

// ---------------------------------------------------------------------------
// Fused attention. grid=(1024,8), 256 threads. fp16 qkv in, f32x2 math.
// ---------------------------------------------------------------------------
#define AP 68
#define ATTN_SMEM ((4 * 64 * AP + 225) * sizeof(float))

__global__ void __launch_bounds__(256)
attn_kernel(const float* __restrict__ mask, const float* __restrict__ logit_scale) {
    const int b = blockIdx.x;
    const int h = blockIdx.y;
    extern __shared__ float smf[];
    float* sqT = smf;                 // [64][AP] q transposed [d][n]
    float* skT = smf + 64 * AP;
    float* sv  = smf + 2 * 64 * AP;   // [n][d]
    float* sp  = smf + 3 * 64 * AP;   // P transposed [j][i]
    float* scpb = smf + 4 * 64 * AP;

    const int tid = threadIdx.x;
    if (tid < 225) scpb[tid] = g_cpb[tid * 8 + h];

    const __half* base = g_qkvh + (size_t)b * NTOK * QKVN + h * HDIM;
#pragma unroll
    for (int it = 0; it < 2; it++) {
        int c = tid + it * 256;           // 0..511
        int n = c >> 3;
        int d8 = (c & 7) << 3;
        const __half* rp = base + (size_t)n * QKVN + d8;
        __half2 qh[4], kh[4], vh[4];
        *(uint4*)qh = *(const uint4*)(rp);
        *(uint4*)kh = *(const uint4*)(rp + CDIM);
        *(uint4*)vh = *(const uint4*)(rp + 2 * CDIM);
        float q[8], k[8], v[8];
#pragma unroll
        for (int j = 0; j < 4; j++) {
            float2 qf = __half22float2(qh[j]);
            float2 kf = __half22float2(kh[j]);
            float2 vf = __half22float2(vh[j]);
            q[j * 2] = qf.x; q[j * 2 + 1] = qf.y;
            k[j * 2] = kf.x; k[j * 2 + 1] = kf.y;
            v[j * 2] = vf.x; v[j * 2 + 1] = vf.y;
        }
        float sq2 = 0.f, sk2 = 0.f;
#pragma unroll
        for (int j = 0; j < 8; j++) { sq2 += q[j] * q[j]; sk2 += k[j] * k[j]; }
#pragma unroll
        for (int o = 4; o; o >>= 1) {
            sq2 += __shfl_xor_sync(0xffffffffu, sq2, o);
            sk2 += __shfl_xor_sync(0xffffffffu, sk2, o);
        }
        float qi = 1.0f / fmaxf(sqrtf(sq2), 1e-12f);
        float ki = 1.0f / fmaxf(sqrtf(sk2), 1e-12f);
#pragma unroll
        for (int j = 0; j < 8; j++) {
            sqT[(d8 + j) * AP + n] = q[j] * qi;
            skT[(d8 + j) * AP + n] = k[j] * ki;
        }
        *(float4*)(sv + n * AP + d8)     = make_float4(v[0], v[1], v[2], v[3]);
        *(float4*)(sv + n * AP + d8 + 4) = make_float4(v[4], v[5], v[6], v[7]);
    }
    __syncthreads();

    const float scale = expf(fminf(logit_scale[h], 4.605170185988091f));
    const int tx = tid & 15, ty = tid >> 4;
    const int i0 = ty * 4, j0 = tx * 4;

    // S = qn @ kn^T with packed f32x2
    unsigned long long acc2[4][2];
#pragma unroll
    for (int i = 0; i < 4; i++) { acc2[i][0] = 0ull; acc2[i][1] = 0ull; }

    for (int kk = 0; kk < 64; kk++) {
        float4 a4 = *(const float4*)(sqT + kk * AP + i0);
        ulonglong2 bb = *(const ulonglong2*)(skT + kk * AP + j0);
        float a[4] = {a4.x, a4.y, a4.z, a4.w};
#pragma unroll
        for (int i = 0; i < 4; i++) {
            unsigned long long aa = pack2(a[i], a[i]);
            fma2(acc2[i][0], aa, bb.x);
            fma2(acc2[i][1], aa, bb.y);
        }
    }

    float acc[4][4];
#pragma unroll
    for (int i = 0; i < 4; i++) {
        unpack2(acc2[i][0], acc[i][0], acc[i][1]);
        unpack2(acc2[i][1], acc[i][2], acc[i][3]);
    }

    const float* mrow = mask + (size_t)(b & 63) * NTOK * NTOK;
#pragma unroll
    for (int i = 0; i < 4; i++) {
        int I = i0 + i;
        float4 m4 = __ldg((const float4*)(mrow + I * 64 + j0));
        float mm[4] = {m4.x, m4.y, m4.z, m4.w};
#pragma unroll
        for (int j = 0; j < 4; j++) {
            int J = j0 + j;
            int t = ((I >> 3) - (J >> 3) + 7) * 15 + ((I & 7) - (J & 7) + 7);
            acc[i][j] = fmaf(acc[i][j], scale, scpb[t]) + mm[j];
        }
    }

#pragma unroll
    for (int i = 0; i < 4; i++) {
        float m = fmaxf(fmaxf(acc[i][0], acc[i][1]), fmaxf(acc[i][2], acc[i][3]));
#pragma unroll
        for (int o = 8; o; o >>= 1) m = fmaxf(m, __shfl_xor_sync(0xffffffffu, m, o));
        float e0 = __expf(acc[i][0] - m);
        float e1 = __expf(acc[i][1] - m);
        float e2 = __expf(acc[i][2] - m);
        float e3 = __expf(acc[i][3] - m);
        float s = e0 + e1 + e2 + e3;
#pragma unroll
        for (int o = 8; o; o >>= 1) s += __shfl_xor_sync(0xffffffffu, s, o);
        float inv = 1.f / s;
        acc[i][0] = e0 * inv; acc[i][1] = e1 * inv;
        acc[i][2] = e2 * inv; acc[i][3] = e3 * inv;
    }

#pragma unroll
    for (int j = 0; j < 4; j++) {
        *(float4*)(sp + (j0 + j) * AP + i0) =
            make_float4(acc[0][j], acc[1][j], acc[2][j], acc[3][j]);
    }
    __syncthreads();

    // O = P @ V with packed f32x2
    unsigned long long o2[4][2];
#pragma unroll
    for (int i = 0; i < 4; i++) { o2[i][0] = 0ull; o2[i][1] = 0ull; }

    for (int jj = 0; jj < 64; jj++) {
        float4 p4 = *(const float4*)(sp + jj * AP + i0);
        ulonglong2 vv = *(const ulonglong2*)(sv + jj * AP + j0);
        float p[4] = {p4.x, p4.y, p4.z, p4.w};
#pragma unroll
        for (int i = 0; i < 4; i++) {
            unsigned long long pp = pack2(p[i], p[i]);
            fma2(o2[i][0], pp, vv.x);
            fma2(o2[i][1], pp, vv.y);
        }
    }

#pragma unroll
    for (int i = 0; i < 4; i++) {
        float o[4];
        unpack2(o2[i][0], o[0], o[1]);
        unpack2(o2[i][1], o[2], o[3]);
        size_t off = ((size_t)(b * NTOK + i0 + i)) * CDIM + h * HDIM + j0;
        __half h0 = __float2half(o[0]);
        __half h1 = __float2half(o[1]);
        __half h2 = __float2half(o[2]);
        __half h3 = __float2half(o[3]);
        __half l0 = __float2half(o[0] - __half2float(h0));
        __half l1 = __float2half(o[1] - __half2float(h1));
        __half l2 = __float2half(o[2] - __half2float(h2));
        __half l3 = __float2half(o[3] - __half2float(h3));
        __half2* hp = (__half2*)(g_ahi + off);
        __half2* lp = (__half2*)(g_alo + off);
        hp[0] = __halves2half2(h0, h1);
        hp[1] = __halves2half2(h2, h3);
        lp[0] = __halves2half2(l0, l1);
        lp[1] = __halves2half2(l2, l3);
    }
}

// ---------------------------------------------------------------------------
// launch
// ---------------------------------------------------------------------------
extern "C" void kernel_launch(void* const* d_in, const int* in_sizes, int n_in,
                              void* d_out, int out_size) {
    const float* x           = (const float*)d_in[0];
    const float* mask        = (const float*)d_in[1];
    const float* qkv_w       = (const float*)d_in[2];
    const float* q_bias      = (const float*)d_in[3];
    const float* v_bias      = (const float*)d_in[4];
    const float* logit_scale = (const float*)d_in[5];
    const float* cpb_w1      = (const float*)d_in[6];
    const float* cpb_b1      = (const float*)d_in[7];
    const float* cpb_w2      = (const float*)d_in[8];
    const float* proj_w      = (const float*)d_in[9];
    const float* proj_b      = (const float*)d_in[10];
    float* out = (float*)d_out;

    float* bias_p;
    __half *qkvh, *xhi, *xlo, *wh, *ph, *ahi, *alo;
    cudaGetSymbolAddress((void**)&qkvh, g_qkvh);
    cudaGetSymbolAddress((void**)&bias_p, g_bias);
    cudaGetSymbolAddress((void**)&xhi, g_xhi);
    cudaGetSymbolAddress((void**)&xlo, g_xlo);
    cudaGetSymbolAddress((void**)&wh, g_wh);
    cudaGetSymbolAddress((void**)&ph, g_ph);
    cudaGetSymbolAddress((void**)&ahi, g_ahi);
    cudaGetSymbolAddress((void**)&alo, g_alo);

    cudaFuncSetAttribute(gemm2h<true>,  cudaFuncAttributeMaxDynamicSharedMemorySize, GEMM_SMEM);
    cudaFuncSetAttribute(gemm2h<false>, cudaFuncAttributeMaxDynamicSharedMemorySize, GEMM_SMEM);
    cudaFuncSetAttribute(attn_kernel, cudaFuncAttributeMaxDynamicSharedMemorySize, (int)ATTN_SMEM);

    // conversions + tables
    conv_hilo_h<<<8192, 256>>>((const float4*)x, xhi, xlo, MTOT * CDIM / 4);
    conv_h2<<<1024, 256>>>((const float4*)qkv_w, wh, QKVN * CDIM / 4,
                           (const float4*)proj_w, ph, CDIM * CDIM / 4);
    cpb_bias_kernel<<<249, 64>>>(cpb_w1, cpb_b1, cpb_w2, q_bias, v_bias);

    // QKV projection -> fp16 qkv: grid (12, 512)
    {
        dim3 grid(QKVN / 128, MTOT / 128);
        gemm2h<true><<<grid, 256, GEMM_SMEM>>>(xhi, xlo, wh, nullptr, qkvh, bias_p, QKVN);
    }

    // fused attention
    {
        dim3 grid(BATCH, NHEAD);
        attn_kernel<<<grid, 256, ATTN_SMEM>>>(mask, logit_scale);
    }

    // output projection -> d_out fp32: grid (4, 512)
    {
        dim3 grid(CDIM / 128, MTOT / 128);
        gemm2h<false><<<grid, 256, GEMM_SMEM>>>(ahi, alo, ph, out, nullptr, proj_b, CDIM);
    }
}

// round 8
// speedup vs baseline: 6.5528x; 1.1861x over previous
#include <cuda_runtime.h>
#include <cuda_fp16.h>
#include <cstdint>

// ---------------------------------------------------------------------------
// Problem constants
// ---------------------------------------------------------------------------
#define BATCH 1024
#define NTOK  64
#define CDIM  512
#define NHEAD 8
#define HDIM  64
#define MTOT  (BATCH * NTOK)      // 65536
#define QKVN  (3 * CDIM)          // 1536

// ---------------------------------------------------------------------------
// Device-global scratch (allocation-free)
// ---------------------------------------------------------------------------
__device__ __align__(16) __half  g_qkvh[(size_t)MTOT * QKVN];   // fp16 qkv
__device__ __align__(16) __half  g_xhi[(size_t)MTOT * CDIM];
__device__ __align__(16) __half  g_xlo[(size_t)MTOT * CDIM];
__device__ __align__(16) __half  g_wh[QKVN * CDIM];
__device__ __align__(16) __half  g_ph[CDIM * CDIM];
__device__ __align__(16) __half  g_ahi[(size_t)MTOT * CDIM];
__device__ __align__(16) __half  g_alo[(size_t)MTOT * CDIM];
__device__ __align__(16) float   g_bias[QKVN];
__device__ __align__(16) float   g_cpb[225 * 8];

// ---------------------------------------------------------------------------
// PTX helpers
// ---------------------------------------------------------------------------
__device__ __forceinline__ uint32_t s2u(const void* p) {
    return (uint32_t)__cvta_generic_to_shared(p);
}
__device__ __forceinline__ void cpa16(uint32_t saddr, const void* g) {
    asm volatile("cp.async.cg.shared.global [%0], [%1], 16;" :: "r"(saddr), "l"(g) : "memory");
}
__device__ __forceinline__ void cpa_commit() {
    asm volatile("cp.async.commit_group;" ::: "memory");
}
__device__ __forceinline__ void cpa_wait0() {
    asm volatile("cp.async.wait_group 0;" ::: "memory");
}
#define LDSM4(r, addr) \
    asm volatile("ldmatrix.sync.aligned.m8n8.x4.shared.b16 {%0,%1,%2,%3}, [%4];" \
        : "=r"((r)[0]), "=r"((r)[1]), "=r"((r)[2]), "=r"((r)[3]) : "r"(addr))
#define LDSM4T(r, addr) \
    asm volatile("ldmatrix.sync.aligned.m8n8.x4.trans.shared.b16 {%0,%1,%2,%3}, [%4];" \
        : "=r"((r)[0]), "=r"((r)[1]), "=r"((r)[2]), "=r"((r)[3]) : "r"(addr))
#define MMAH16816(c, a, b0, b1) \
    asm volatile("mma.sync.aligned.m16n8k16.row.col.f32.f16.f16.f32 " \
        "{%0,%1,%2,%3},{%4,%5,%6,%7},{%8,%9},{%0,%1,%2,%3};" \
        : "+f"((c)[0]), "+f"((c)[1]), "+f"((c)[2]), "+f"((c)[3]) \
        : "r"((a)[0]), "r"((a)[1]), "r"((a)[2]), "r"((a)[3]), "r"(b0), "r"(b1))

__device__ __forceinline__ uint32_t h2u(__half2 v) { return *(uint32_t*)&v; }

// ---------------------------------------------------------------------------
// fp32 -> fp16 hi/lo split (x)
// ---------------------------------------------------------------------------
__global__ void conv_hilo_h(const float4* __restrict__ in, __half* __restrict__ hi,
                            __half* __restrict__ lo, int n4) {
    int stride = gridDim.x * blockDim.x;
    for (int i = blockIdx.x * blockDim.x + threadIdx.x; i < n4; i += stride) {
        float4 v = in[i];
        __half h0 = __float2half(v.x), h1 = __float2half(v.y);
        __half h2 = __float2half(v.z), h3 = __float2half(v.w);
        __half l0 = __float2half(v.x - __half2float(h0));
        __half l1 = __float2half(v.y - __half2float(h1));
        __half l2 = __float2half(v.z - __half2float(h2));
        __half l3 = __float2half(v.w - __half2float(h3));
        __half2* hp = (__half2*)(hi + (size_t)i * 4);
        __half2* lp = (__half2*)(lo + (size_t)i * 4);
        hp[0] = __halves2half2(h0, h1);
        hp[1] = __halves2half2(h2, h3);
        lp[0] = __halves2half2(l0, l1);
        lp[1] = __halves2half2(l2, l3);
    }
}

// both weight conversions in one launch
__global__ void conv_h2(const float4* __restrict__ w, __half* __restrict__ wh, int n4w,
                        const float4* __restrict__ p, __half* __restrict__ ph, int n4p) {
    int stride = gridDim.x * blockDim.x;
    int total = n4w + n4p;
    for (int i = blockIdx.x * blockDim.x + threadIdx.x; i < total; i += stride) {
        const float4* src; __half* dst; int idx;
        if (i < n4w) { src = w; dst = wh; idx = i; }
        else         { src = p; dst = ph; idx = i - n4w; }
        float4 v = src[idx];
        __half2* op = (__half2*)(dst + (size_t)idx * 4);
        op[0] = __halves2half2(__float2half(v.x), __float2half(v.y));
        op[1] = __halves2half2(__float2half(v.z), __float2half(v.w));
    }
}

// ---------------------------------------------------------------------------
// CPB MLP + bias build in one launch
// ---------------------------------------------------------------------------
__device__ __forceinline__ float signed_log_coord(int d) {
    float g = (float)d / 7.0f * 8.0f;
    float s = (g > 0.f) ? 1.f : ((g < 0.f) ? -1.f : 0.f);
    return s * log2f(fabsf(g) + 1.0f) / log2f(9.0f);
}
__global__ void cpb_bias_kernel(const float* __restrict__ w1, const float* __restrict__ b1,
                                const float* __restrict__ w2,
                                const float* __restrict__ qb, const float* __restrict__ vb) {
    int t = blockIdx.x;
    if (t >= 225) {
        int i = (t - 225) * 64 + threadIdx.x;
        if (threadIdx.x < 64 && i < QKVN)
            g_bias[i] = (i < 512) ? qb[i] : ((i < 1024) ? 0.f : vb[i - 1024]);
        return;
    }
    float c0 = signed_log_coord(t / 15 - 7);
    float c1 = signed_log_coord(t % 15 - 7);
    __shared__ float red[64][8];
    float p[8];
#pragma unroll
    for (int h = 0; h < 8; h++) p[h] = 0.f;
    for (int j = threadIdx.x; j < 512; j += 64) {
        float hx = fmaf(c0, w1[2 * j], fmaf(c1, w1[2 * j + 1], b1[j]));
        hx = fmaxf(hx, 0.f);
#pragma unroll
        for (int h = 0; h < 8; h++) p[h] += hx * w2[h * 512 + j];
    }
#pragma unroll
    for (int h = 0; h < 8; h++) red[threadIdx.x][h] = p[h];
    __syncthreads();
    if (threadIdx.x < 8) {
        float s = 0.f;
#pragma unroll
        for (int i = 0; i < 64; i++) s += red[i][threadIdx.x];
        g_cpb[t * 8 + threadIdx.x] = 16.f / (1.f + expf(-s));
    }
}

// ---------------------------------------------------------------------------
// HMMA GEMM (fp16 2-pass): C[M,N] = (Ah+Al)[M,512] @ B[N,512]^T + bias[n]
// Tile 128x128x64, 8 warps (2x4), 2-stage cp.async, 2 CTAs/SM.
// ---------------------------------------------------------------------------
#define LDT 144                      // 128 B data + 16 pad per row
#define TILE_BYTES (128 * LDT)       // 18432
#define A_HI 0
#define A_LO TILE_BYTES
#define B_OF (2 * TILE_BYTES)
#define SS (3 * TILE_BYTES)          // 55296 per stage
#define GEMM_SMEM (2 * SS)           // 110592

__device__ __forceinline__ void load_stage(
    uint32_t sbase, int kt,
    const __half* __restrict__ Ah, const __half* __restrict__ Al,
    const __half* __restrict__ B,
    int m0, int n0, int tid) {
    const int k0 = kt * 64;
#pragma unroll
    for (int i = 0; i < 4; i++) {
        int id = tid + i * 256;
        int r = id >> 3, c = id & 7;
        uint32_t so = (uint32_t)(r * LDT + c * 16);
        size_t ga = (size_t)(m0 + r) * CDIM + k0 + c * 8;
        size_t gb = (size_t)(n0 + r) * CDIM + k0 + c * 8;
        cpa16(sbase + A_HI + so, Ah + ga);
        cpa16(sbase + A_LO + so, Al + ga);
        cpa16(sbase + B_OF + so, B + gb);
    }
    cpa_commit();
}

template <bool HALF_OUT>
__global__ void __launch_bounds__(256, 2)
gemm2h(const __half* __restrict__ Ah, const __half* __restrict__ Al,
       const __half* __restrict__ B,
       float* __restrict__ Cf, __half* __restrict__ Ch,
       const float* __restrict__ bias, int ldc) {
    extern __shared__ char dsm[];
    const uint32_t smb = s2u(dsm);

    const int tid = threadIdx.x;
    const int wid = tid >> 5;
    const int lane = tid & 31;
    const int wm = wid >> 2;
    const int wn = wid & 3;
    const int m0 = blockIdx.y * 128;
    const int n0 = blockIdx.x * 128;

    float acc[16][4];
#pragma unroll
    for (int t = 0; t < 16; t++)
#pragma unroll
        for (int e = 0; e < 4; e++) acc[t][e] = 0.f;

    load_stage(smb, 0, Ah, Al, B, m0, n0, tid);

    const uint32_t a_row = (uint32_t)((wm * 64 + (lane & 15)) * LDT + (lane >> 4) * 16);
    const uint32_t b_row = (uint32_t)((wn * 32 + (lane & 7) + ((lane >> 4) << 3)) * LDT
                                      + ((lane >> 3) & 1) * 16);

    const int NK = CDIM / 64;  // 8
    for (int kt = 0; kt < NK; kt++) {
        cpa_wait0();
        __syncthreads();
        if (kt + 1 < NK)
            load_stage(smb + (uint32_t)((kt + 1) & 1) * SS, kt + 1, Ah, Al, B, m0, n0, tid);

        const uint32_t st = smb + (uint32_t)(kt & 1) * SS;
#pragma unroll
        for (int ks = 0; ks < 4; ks++) {
            const uint32_t koff = (uint32_t)(ks * 32);
            uint32_t bh[2][4];
#pragma unroll
            for (int nf = 0; nf < 2; nf++) {
                uint32_t bd = st + b_row + (uint32_t)(nf * 16 * LDT) + koff;
                LDSM4(bh[nf], bd + B_OF);
            }
#pragma unroll
            for (int i = 0; i < 4; i++) {
                uint32_t ah[4], al[4];
                uint32_t ad = st + a_row + (uint32_t)(i * 16 * LDT) + koff;
                LDSM4(ah, ad + A_HI);
                LDSM4(al, ad + A_LO);
#pragma unroll
                for (int j = 0; j < 4; j++) {
                    float* c = acc[i * 4 + j];
                    int nf = j >> 1, sb = (j & 1) * 2;
                    MMAH16816(c, ah, bh[nf][sb], bh[nf][sb + 1]);
                    MMAH16816(c, al, bh[nf][sb], bh[nf][sb + 1]);
                }
            }
        }
    }

#pragma unroll
    for (int i = 0; i < 4; i++) {
#pragma unroll
        for (int j = 0; j < 4; j++) {
            const float* c = acc[i * 4 + j];
            int row = m0 + wm * 64 + i * 16 + (lane >> 2);
            int col = n0 + wn * 32 + j * 8 + (lane & 3) * 2;
            float2 b2 = __ldg((const float2*)(bias + col));
            if (HALF_OUT) {
                __half2 v0 = __floats2half2_rn(c[0] + b2.x, c[1] + b2.y);
                __half2 v1 = __floats2half2_rn(c[2] + b2.x, c[3] + b2.y);
                *(__half2*)(Ch + (size_t)row * ldc + col) = v0;
                *(__half2*)(Ch + (size_t)(row + 8) * ldc + col) = v1;
            } else {
                float2 v0 = make_float2(c[0] + b2.x, c[1] + b2.y);
                float2 v1 = make_float2(c[2] + b2.x, c[3] + b2.y);
                *(float2*)(Cf + (size_t)row * ldc + col) = v0;
                *(float2*)(Cf + (size_t)(row + 8) * ldc + col) = v1;
            }
        }
    }
}

// ---------------------------------------------------------------------------
// HMMA fused attention. grid=(1024,8), 128 threads (4 warps, 16 rows each).
// Deferred normalization: S_raw = q@k^T (fp16 MMA), scaled by rinv in fp32.
// ---------------------------------------------------------------------------
#define LDV 72    // halves per smem row (144 B): conflict-free ldmatrix phases
#define ATTN_SMEM (3 * 64 * LDV * 2 + (64 + 64 + 225) * 4)

__global__ void __launch_bounds__(128)
attn_mma(const float* __restrict__ mask, const float* __restrict__ logit_scale) {
    const int b = blockIdx.x;
    const int h = blockIdx.y;
    extern __shared__ char smc[];
    __half* sq = (__half*)smc;
    __half* sk = sq + 64 * LDV;
    __half* sv = sk + 64 * LDV;
    float* rq = (float*)(sv + 64 * LDV);
    float* rk = rq + 64;
    float* scpb = rk + 64;

    const int tid = threadIdx.x;
    const int wid = tid >> 5;
    const int lane = tid & 31;

    // load q,k,v fp16 tiles
    const __half* gbase = g_qkvh + (size_t)b * NTOK * QKVN + h * HDIM;
#pragma unroll
    for (int i = 0; i < 4; i++) {
        int idx = tid + i * 128;          // 0..511
        int r = idx >> 3, c = idx & 7;
        const __half* rp = gbase + (size_t)r * QKVN + c * 8;
        uint4 qv = *(const uint4*)(rp);
        uint4 kv = *(const uint4*)(rp + CDIM);
        uint4 vv = *(const uint4*)(rp + 2 * CDIM);
        *(uint4*)(sq + r * LDV + c * 8) = qv;
        *(uint4*)(sk + r * LDV + c * 8) = kv;
        *(uint4*)(sv + r * LDV + c * 8) = vv;
    }
    for (int i = tid; i < 225; i += 128) scpb[i] = g_cpb[i * 8 + h];
    __syncthreads();

    // inverse row norms: threads 0-63 -> q rows, 64-127 -> k rows
    {
        int r = tid & 63;
        const __half* row = (tid < 64 ? sq : sk) + r * LDV;
        float s0 = 0.f, s1 = 0.f;
#pragma unroll
        for (int c = 0; c < 8; c++) {
            uint4 u = *(const uint4*)(row + c * 8);
            const __half2* hp = (const __half2*)&u;
#pragma unroll
            for (int t2 = 0; t2 < 4; t2++) {
                float2 f = __half22float2(hp[t2]);
                s0 = fmaf(f.x, f.x, s0);
                s1 = fmaf(f.y, f.y, s1);
            }
        }
        float inv = 1.f / fmaxf(sqrtf(s0 + s1), 1e-12f);
        (tid < 64 ? rq : rk)[r] = inv;
    }
    __syncthreads();

    const int r0 = wid * 16;
    const uint32_t qbase = s2u(sq) +
        (uint32_t)(((r0 + (lane & 15)) * LDV + ((lane >> 4) & 1) * 8) * 2);
    const uint32_t kbase = s2u(sk) +
        (uint32_t)((((lane & 7) + ((lane >> 4) << 3)) * LDV + ((lane >> 3) & 1) * 8) * 2);

    // S = q @ k^T  (raw, fp16 MMA, fp32 accum)
    float sacc[8][4];
#pragma unroll
    for (int f = 0; f < 8; f++)
#pragma unroll
        for (int e = 0; e < 4; e++) sacc[f][e] = 0.f;

#pragma unroll
    for (int kg = 0; kg < 4; kg++) {
        uint32_t aq[4];
        LDSM4(aq, qbase + (uint32_t)(kg * 32));
#pragma unroll
        for (int ng = 0; ng < 4; ng++) {
            uint32_t bk[4];
            LDSM4(bk, kbase + (uint32_t)(ng * 16 * LDV * 2 + kg * 32));
            MMAH16816(sacc[ng * 2],     aq, bk[0], bk[1]);
            MMAH16816(sacc[ng * 2 + 1], aq, bk[2], bk[3]);
        }
    }

    // scale by rinv_q * rinv_k * logit_scale, add cpb + mask
    const float sc = expf(fminf(logit_scale[h], 4.605170185988091f));
    const int rlo = r0 + (lane >> 2);
    const int rhi = rlo + 8;
    const float qlo = rq[rlo] * sc;
    const float qhi = rq[rhi] * sc;
    const float* mrow = mask + (size_t)(b & 63) * NTOK * NTOK;
#pragma unroll
    for (int nf = 0; nf < 8; nf++) {
        int c0 = nf * 8 + (lane & 3) * 2;
        float rk0 = rk[c0], rk1 = rk[c0 + 1];
        float2 mlo2 = __ldg((const float2*)(mrow + rlo * 64 + c0));
        float2 mhi2 = __ldg((const float2*)(mrow + rhi * 64 + c0));
        int tlo = ((rlo >> 3) - (c0 >> 3) + 7) * 15 + ((rlo & 7) - (c0 & 7) + 7);
        int thi = tlo + 15;   // rhi = rlo + 8 bumps the block-row term by 1
        sacc[nf][0] = sacc[nf][0] * qlo * rk0 + scpb[tlo] + mlo2.x;
        sacc[nf][1] = sacc[nf][1] * qlo * rk1 + scpb[tlo - 1] + mlo2.y;
        sacc[nf][2] = sacc[nf][2] * qhi * rk0 + scpb[thi] + mhi2.x;
        sacc[nf][3] = sacc[nf][3] * qhi * rk1 + scpb[thi - 1] + mhi2.y;
    }

    // register softmax (rows rlo / rhi, 4-lane groups share a row)
    float mlo = -1e30f, mhi = -1e30f;
#pragma unroll
    for (int nf = 0; nf < 8; nf++) {
        mlo = fmaxf(mlo, fmaxf(sacc[nf][0], sacc[nf][1]));
        mhi = fmaxf(mhi, fmaxf(sacc[nf][2], sacc[nf][3]));
    }
#pragma unroll
    for (int o = 1; o <= 2; o <<= 1) {
        mlo = fmaxf(mlo, __shfl_xor_sync(0xffffffffu, mlo, o));
        mhi = fmaxf(mhi, __shfl_xor_sync(0xffffffffu, mhi, o));
    }
    float slo = 0.f, shi = 0.f;
#pragma unroll
    for (int nf = 0; nf < 8; nf++) {
        sacc[nf][0] = __expf(sacc[nf][0] - mlo); slo += sacc[nf][0];
        sacc[nf][1] = __expf(sacc[nf][1] - mlo); slo += sacc[nf][1];
        sacc[nf][2] = __expf(sacc[nf][2] - mhi); shi += sacc[nf][2];
        sacc[nf][3] = __expf(sacc[nf][3] - mhi); shi += sacc[nf][3];
    }
#pragma unroll
    for (int o = 1; o <= 2; o <<= 1) {
        slo += __shfl_xor_sync(0xffffffffu, slo, o);
        shi += __shfl_xor_sync(0xffffffffu, shi, o);
    }
    const float ilo = 1.f / slo, ihi = 1.f / shi;

    // P c-frags -> fp16 A-frags (pure register repack)
    uint32_t pa[4][4];
#pragma unroll
    for (int g = 0; g < 4; g++) {
        pa[g][0] = h2u(__floats2half2_rn(sacc[2 * g][0] * ilo, sacc[2 * g][1] * ilo));
        pa[g][1] = h2u(__floats2half2_rn(sacc[2 * g][2] * ihi, sacc[2 * g][3] * ihi));
        pa[g][2] = h2u(__floats2half2_rn(sacc[2 * g + 1][0] * ilo, sacc[2 * g + 1][1] * ilo));
        pa[g][3] = h2u(__floats2half2_rn(sacc[2 * g + 1][2] * ihi, sacc[2 * g + 1][3] * ihi));
    }

    // O = P @ V  (V via ldmatrix.trans)
    float oacc[8][4];
#pragma unroll
    for (int f = 0; f < 8; f++)
#pragma unroll
        for (int e = 0; e < 4; e++) oacc[f][e] = 0.f;

    const uint32_t vbase = s2u(sv) +
        (uint32_t)(((lane & 15) * LDV + ((lane >> 4) & 1) * 8) * 2);
#pragma unroll
    for (int kg = 0; kg < 4; kg++) {
#pragma unroll
        for (int ng = 0; ng < 4; ng++) {
            uint32_t bv[4];
            LDSM4T(bv, vbase + (uint32_t)(kg * 16 * LDV * 2 + ng * 32));
            MMAH16816(oacc[ng * 2],     pa[kg], bv[0], bv[1]);
            MMAH16816(oacc[ng * 2 + 1], pa[kg], bv[2], bv[3]);
        }
    }

    // write O as fp16 hi/lo (input to proj GEMM)
#pragma unroll
    for (int nf = 0; nf < 8; nf++) {
        int col = h * HDIM + nf * 8 + (lane & 3) * 2;
        size_t offlo = (size_t)(b * NTOK + rlo) * CDIM + col;
        size_t offhi = (size_t)(b * NTOK + rhi) * CDIM + col;
        float o0 = oacc[nf][0], o1 = oacc[nf][1];
        float o2 = oacc[nf][2], o3 = oacc[nf][3];
        __half a0 = __float2half(o0), a1 = __float2half(o1);
        __half a2 = __float2half(o2), a3 = __float2half(o3);
        *(__half2*)(g_ahi + offlo) = __halves2half2(a0, a1);
        *(__half2*)(g_ahi + offhi) = __halves2half2(a2, a3);
        *(__half2*)(g_alo + offlo) = __halves2half2(
            __float2half(o0 - __half2float(a0)), __float2half(o1 - __half2float(a1)));
        *(__half2*)(g_alo + offhi) = __halves2half2(
            __float2half(o2 - __half2float(a2)), __float2half(o3 - __half2float(a3)));
    }
}

// ---------------------------------------------------------------------------
// launch
// ---------------------------------------------------------------------------
extern "C" void kernel_launch(void* const* d_in, const int* in_sizes, int n_in,
                              void* d_out, int out_size) {
    const float* x           = (const float*)d_in[0];
    const float* mask        = (const float*)d_in[1];
    const float* qkv_w       = (const float*)d_in[2];
    const float* q_bias      = (const float*)d_in[3];
    const float* v_bias      = (const float*)d_in[4];
    const float* logit_scale = (const float*)d_in[5];
    const float* cpb_w1      = (const float*)d_in[6];
    const float* cpb_b1      = (const float*)d_in[7];
    const float* cpb_w2      = (const float*)d_in[8];
    const float* proj_w      = (const float*)d_in[9];
    const float* proj_b      = (const float*)d_in[10];
    float* out = (float*)d_out;

    float* bias_p;
    __half *qkvh, *xhi, *xlo, *wh, *ph, *ahi, *alo;
    cudaGetSymbolAddress((void**)&qkvh, g_qkvh);
    cudaGetSymbolAddress((void**)&bias_p, g_bias);
    cudaGetSymbolAddress((void**)&xhi, g_xhi);
    cudaGetSymbolAddress((void**)&xlo, g_xlo);
    cudaGetSymbolAddress((void**)&wh, g_wh);
    cudaGetSymbolAddress((void**)&ph, g_ph);
    cudaGetSymbolAddress((void**)&ahi, g_ahi);
    cudaGetSymbolAddress((void**)&alo, g_alo);

    cudaFuncSetAttribute(gemm2h<true>,  cudaFuncAttributeMaxDynamicSharedMemorySize, GEMM_SMEM);
    cudaFuncSetAttribute(gemm2h<false>, cudaFuncAttributeMaxDynamicSharedMemorySize, GEMM_SMEM);
    cudaFuncSetAttribute(attn_mma, cudaFuncAttributeMaxDynamicSharedMemorySize, ATTN_SMEM);

    // conversions + tables
    conv_hilo_h<<<8192, 256>>>((const float4*)x, xhi, xlo, MTOT * CDIM / 4);
    conv_h2<<<1024, 256>>>((const float4*)qkv_w, wh, QKVN * CDIM / 4,
                           (const float4*)proj_w, ph, CDIM * CDIM / 4);
    cpb_bias_kernel<<<249, 64>>>(cpb_w1, cpb_b1, cpb_w2, q_bias, v_bias);

    // QKV projection -> fp16 qkv: grid (12, 512)
    {
        dim3 grid(QKVN / 128, MTOT / 128);
        gemm2h<true><<<grid, 256, GEMM_SMEM>>>(xhi, xlo, wh, nullptr, qkvh, bias_p, QKVN);
    }

    // fused HMMA attention
    {
        dim3 grid(BATCH, NHEAD);
        attn_mma<<<grid, 128, ATTN_SMEM>>>(mask, logit_scale);
    }

    // output projection -> d_out fp32: grid (4, 512)
    {
        dim3 grid(CDIM / 128, MTOT / 128);
        gemm2h<false><<<grid, 256, GEMM_SMEM>>>(ahi, alo, ph, out, nullptr, proj_b, CDIM);
    }
}

// round 9
// speedup vs baseline: 6.6895x; 1.0209x over previous
#include <cuda_runtime.h>
#include <cuda_fp16.h>
#include <cstdint>

// ---------------------------------------------------------------------------
// Problem constants
// ---------------------------------------------------------------------------
#define BATCH 1024
#define NTOK  64
#define CDIM  512
#define NHEAD 8
#define HDIM  64
#define MTOT  (BATCH * NTOK)      // 65536
#define QKVN  (3 * CDIM)          // 1536

// ---------------------------------------------------------------------------
// Device-global scratch (allocation-free)
// ---------------------------------------------------------------------------
__device__ __align__(16) __half  g_qkvh[(size_t)MTOT * QKVN];   // fp16 qkv
__device__ __align__(16) __half  g_xhi[(size_t)MTOT * CDIM];
__device__ __align__(16) __half  g_xlo[(size_t)MTOT * CDIM];
__device__ __align__(16) __half  g_wh[QKVN * CDIM];
__device__ __align__(16) __half  g_ph[CDIM * CDIM];
__device__ __align__(16) __half  g_ahi[(size_t)MTOT * CDIM];
__device__ __align__(16) __half  g_alo[(size_t)MTOT * CDIM];
__device__ __align__(16) float   g_bias[QKVN];
__device__ __align__(16) float   g_cpb[225 * 8];

// ---------------------------------------------------------------------------
// PTX helpers
// ---------------------------------------------------------------------------
__device__ __forceinline__ uint32_t s2u(const void* p) {
    return (uint32_t)__cvta_generic_to_shared(p);
}
__device__ __forceinline__ void cpa16(uint32_t saddr, const void* g) {
    asm volatile("cp.async.cg.shared.global [%0], [%1], 16;" :: "r"(saddr), "l"(g) : "memory");
}
__device__ __forceinline__ void cpa_commit() {
    asm volatile("cp.async.commit_group;" ::: "memory");
}
__device__ __forceinline__ void cpa_wait0() {
    asm volatile("cp.async.wait_group 0;" ::: "memory");
}
#define LDSM4(r, addr) \
    asm volatile("ldmatrix.sync.aligned.m8n8.x4.shared.b16 {%0,%1,%2,%3}, [%4];" \
        : "=r"((r)[0]), "=r"((r)[1]), "=r"((r)[2]), "=r"((r)[3]) : "r"(addr))
#define LDSM4T(r, addr) \
    asm volatile("ldmatrix.sync.aligned.m8n8.x4.trans.shared.b16 {%0,%1,%2,%3}, [%4];" \
        : "=r"((r)[0]), "=r"((r)[1]), "=r"((r)[2]), "=r"((r)[3]) : "r"(addr))
#define MMAH16816(c, a, b0, b1) \
    asm volatile("mma.sync.aligned.m16n8k16.row.col.f32.f16.f16.f32 " \
        "{%0,%1,%2,%3},{%4,%5,%6,%7},{%8,%9},{%0,%1,%2,%3};" \
        : "+f"((c)[0]), "+f"((c)[1]), "+f"((c)[2]), "+f"((c)[3]) \
        : "r"((a)[0]), "r"((a)[1]), "r"((a)[2]), "r"((a)[3]), "r"(b0), "r"(b1))

__device__ __forceinline__ uint32_t h2u(__half2 v) { return *(uint32_t*)&v; }

// ---------------------------------------------------------------------------
// fp32 -> fp16 hi/lo split (x)
// ---------------------------------------------------------------------------
__global__ void conv_hilo_h(const float4* __restrict__ in, __half* __restrict__ hi,
                            __half* __restrict__ lo, int n4) {
    int stride = gridDim.x * blockDim.x;
    for (int i = blockIdx.x * blockDim.x + threadIdx.x; i < n4; i += stride) {
        float4 v = in[i];
        __half h0 = __float2half(v.x), h1 = __float2half(v.y);
        __half h2 = __float2half(v.z), h3 = __float2half(v.w);
        __half l0 = __float2half(v.x - __half2float(h0));
        __half l1 = __float2half(v.y - __half2float(h1));
        __half l2 = __float2half(v.z - __half2float(h2));
        __half l3 = __float2half(v.w - __half2float(h3));
        __half2* hp = (__half2*)(hi + (size_t)i * 4);
        __half2* lp = (__half2*)(lo + (size_t)i * 4);
        hp[0] = __halves2half2(h0, h1);
        hp[1] = __halves2half2(h2, h3);
        lp[0] = __halves2half2(l0, l1);
        lp[1] = __halves2half2(l2, l3);
    }
}

// both weight conversions in one launch
__global__ void conv_h2(const float4* __restrict__ w, __half* __restrict__ wh, int n4w,
                        const float4* __restrict__ p, __half* __restrict__ ph, int n4p) {
    int stride = gridDim.x * blockDim.x;
    int total = n4w + n4p;
    for (int i = blockIdx.x * blockDim.x + threadIdx.x; i < total; i += stride) {
        const float4* src; __half* dst; int idx;
        if (i < n4w) { src = w; dst = wh; idx = i; }
        else         { src = p; dst = ph; idx = i - n4w; }
        float4 v = src[idx];
        __half2* op = (__half2*)(dst + (size_t)idx * 4);
        op[0] = __halves2half2(__float2half(v.x), __float2half(v.y));
        op[1] = __halves2half2(__float2half(v.z), __float2half(v.w));
    }
}

// ---------------------------------------------------------------------------
// CPB MLP + bias build in one launch
// ---------------------------------------------------------------------------
__device__ __forceinline__ float signed_log_coord(int d) {
    float g = (float)d / 7.0f * 8.0f;
    float s = (g > 0.f) ? 1.f : ((g < 0.f) ? -1.f : 0.f);
    return s * log2f(fabsf(g) + 1.0f) / log2f(9.0f);
}
__global__ void cpb_bias_kernel(const float* __restrict__ w1, const float* __restrict__ b1,
                                const float* __restrict__ w2,
                                const float* __restrict__ qb, const float* __restrict__ vb) {
    int t = blockIdx.x;
    if (t >= 225) {
        int i = (t - 225) * 64 + threadIdx.x;
        if (threadIdx.x < 64 && i < QKVN)
            g_bias[i] = (i < 512) ? qb[i] : ((i < 1024) ? 0.f : vb[i - 1024]);
        return;
    }
    float c0 = signed_log_coord(t / 15 - 7);
    float c1 = signed_log_coord(t % 15 - 7);
    __shared__ float red[64][8];
    float p[8];
#pragma unroll
    for (int h = 0; h < 8; h++) p[h] = 0.f;
    for (int j = threadIdx.x; j < 512; j += 64) {
        float hx = fmaf(c0, w1[2 * j], fmaf(c1, w1[2 * j + 1], b1[j]));
        hx = fmaxf(hx, 0.f);
#pragma unroll
        for (int h = 0; h < 8; h++) p[h] += hx * w2[h * 512 + j];
    }
#pragma unroll
    for (int h = 0; h < 8; h++) red[threadIdx.x][h] = p[h];
    __syncthreads();
    if (threadIdx.x < 8) {
        float s = 0.f;
#pragma unroll
        for (int i = 0; i < 64; i++) s += red[i][threadIdx.x];
        g_cpb[t * 8 + threadIdx.x] = 16.f / (1.f + expf(-s));
    }
}

// ---------------------------------------------------------------------------
// HMMA GEMM (fp16 2-pass): C[M,N] = (Ah+Al)[M,512] @ B[N,512]^T + bias[n]
// Tile 128x128x64, 8 warps as 4x2 (warp tile 32x64) — minimizes LDSM traffic.
// 2-stage cp.async, 2 CTAs/SM.
// ---------------------------------------------------------------------------
#define LDT 144                      // 128 B data + 16 pad per row
#define TILE_BYTES (128 * LDT)       // 18432
#define A_HI 0
#define A_LO TILE_BYTES
#define B_OF (2 * TILE_BYTES)
#define SS (3 * TILE_BYTES)          // 55296 per stage
#define GEMM_SMEM (2 * SS)           // 110592

__device__ __forceinline__ void load_stage(
    uint32_t sbase, int kt,
    const __half* __restrict__ Ah, const __half* __restrict__ Al,
    const __half* __restrict__ B,
    int m0, int n0, int tid) {
    const int k0 = kt * 64;
#pragma unroll
    for (int i = 0; i < 4; i++) {
        int id = tid + i * 256;
        int r = id >> 3, c = id & 7;
        uint32_t so = (uint32_t)(r * LDT + c * 16);
        size_t ga = (size_t)(m0 + r) * CDIM + k0 + c * 8;
        size_t gb = (size_t)(n0 + r) * CDIM + k0 + c * 8;
        cpa16(sbase + A_HI + so, Ah + ga);
        cpa16(sbase + A_LO + so, Al + ga);
        cpa16(sbase + B_OF + so, B + gb);
    }
    cpa_commit();
}

template <bool HALF_OUT>
__global__ void __launch_bounds__(256, 2)
gemm2h(const __half* __restrict__ Ah, const __half* __restrict__ Al,
       const __half* __restrict__ B,
       float* __restrict__ Cf, __half* __restrict__ Ch,
       const float* __restrict__ bias, int ldc) {
    extern __shared__ char dsm[];
    const uint32_t smb = s2u(dsm);

    const int tid = threadIdx.x;
    const int wid = tid >> 5;
    const int lane = tid & 31;
    const int wm = wid & 3;           // 4 m-warps: rows wm*32
    const int wn = wid >> 2;          // 2 n-warps: cols wn*64
    const int m0 = blockIdx.y * 128;
    const int n0 = blockIdx.x * 128;

    float acc[16][4];
#pragma unroll
    for (int t = 0; t < 16; t++)
#pragma unroll
        for (int e = 0; e < 4; e++) acc[t][e] = 0.f;

    load_stage(smb, 0, Ah, Al, B, m0, n0, tid);

    const uint32_t a_row = (uint32_t)((wm * 32 + (lane & 15)) * LDT + (lane >> 4) * 16);
    const uint32_t b_row = (uint32_t)((wn * 64 + (lane & 7) + ((lane >> 4) << 3)) * LDT
                                      + ((lane >> 3) & 1) * 16);

    const int NK = CDIM / 64;  // 8
    for (int kt = 0; kt < NK; kt++) {
        cpa_wait0();
        __syncthreads();
        if (kt + 1 < NK)
            load_stage(smb + (uint32_t)((kt + 1) & 1) * SS, kt + 1, Ah, Al, B, m0, n0, tid);

        const uint32_t st = smb + (uint32_t)(kt & 1) * SS;
#pragma unroll
        for (int ks = 0; ks < 4; ks++) {
            const uint32_t koff = (uint32_t)(ks * 32);
            uint32_t bh[4][4];
#pragma unroll
            for (int ng = 0; ng < 4; ng++) {
                uint32_t bd = st + b_row + (uint32_t)(ng * 16 * LDT) + koff;
                LDSM4(bh[ng], bd + B_OF);
            }
#pragma unroll
            for (int i = 0; i < 2; i++) {
                uint32_t ah[4], al[4];
                uint32_t ad = st + a_row + (uint32_t)(i * 16 * LDT) + koff;
                LDSM4(ah, ad + A_HI);
                LDSM4(al, ad + A_LO);
#pragma unroll
                for (int j = 0; j < 8; j++) {
                    float* c = acc[i * 8 + j];
                    int ng = j >> 1, sb = (j & 1) * 2;
                    MMAH16816(c, ah, bh[ng][sb], bh[ng][sb + 1]);
                    MMAH16816(c, al, bh[ng][sb], bh[ng][sb + 1]);
                }
            }
        }
    }

#pragma unroll
    for (int i = 0; i < 2; i++) {
#pragma unroll
        for (int j = 0; j < 8; j++) {
            const float* c = acc[i * 8 + j];
            int row = m0 + wm * 32 + i * 16 + (lane >> 2);
            int col = n0 + wn * 64 + j * 8 + (lane & 3) * 2;
            float2 b2 = __ldg((const float2*)(bias + col));
            if (HALF_OUT) {
                __half2 v0 = __floats2half2_rn(c[0] + b2.x, c[1] + b2.y);
                __half2 v1 = __floats2half2_rn(c[2] + b2.x, c[3] + b2.y);
                *(__half2*)(Ch + (size_t)row * ldc + col) = v0;
                *(__half2*)(Ch + (size_t)(row + 8) * ldc + col) = v1;
            } else {
                float2 v0 = make_float2(c[0] + b2.x, c[1] + b2.y);
                float2 v1 = make_float2(c[2] + b2.x, c[3] + b2.y);
                *(float2*)(Cf + (size_t)row * ldc + col) = v0;
                *(float2*)(Cf + (size_t)(row + 8) * ldc + col) = v1;
            }
        }
    }
}

// ---------------------------------------------------------------------------
// HMMA fused attention. grid=(1024,8), 128 threads (4 warps, 16 rows each).
// Deferred normalization: S_raw = q@k^T (fp16 MMA), scaled by rinv in fp32.
// ---------------------------------------------------------------------------
#define LDV 72    // halves per smem row (144 B): conflict-free ldmatrix phases
#define ATTN_SMEM (3 * 64 * LDV * 2 + (64 + 64 + 225) * 4)

__global__ void __launch_bounds__(128)
attn_mma(const float* __restrict__ mask, const float* __restrict__ logit_scale) {
    const int b = blockIdx.x;
    const int h = blockIdx.y;
    extern __shared__ char smc[];
    __half* sq = (__half*)smc;
    __half* sk = sq + 64 * LDV;
    __half* sv = sk + 64 * LDV;
    float* rq = (float*)(sv + 64 * LDV);
    float* rk = rq + 64;
    float* scpb = rk + 64;

    const int tid = threadIdx.x;
    const int wid = tid >> 5;
    const int lane = tid & 31;

    // load q,k,v fp16 tiles
    const __half* gbase = g_qkvh + (size_t)b * NTOK * QKVN + h * HDIM;
#pragma unroll
    for (int i = 0; i < 4; i++) {
        int idx = tid + i * 128;          // 0..511
        int r = idx >> 3, c = idx & 7;
        const __half* rp = gbase + (size_t)r * QKVN + c * 8;
        uint4 qv = *(const uint4*)(rp);
        uint4 kv = *(const uint4*)(rp + CDIM);
        uint4 vv = *(const uint4*)(rp + 2 * CDIM);
        *(uint4*)(sq + r * LDV + c * 8) = qv;
        *(uint4*)(sk + r * LDV + c * 8) = kv;
        *(uint4*)(sv + r * LDV + c * 8) = vv;
    }
    for (int i = tid; i < 225; i += 128) scpb[i] = g_cpb[i * 8 + h];
    __syncthreads();

    // inverse row norms: threads 0-63 -> q rows, 64-127 -> k rows
    {
        int r = tid & 63;
        const __half* row = (tid < 64 ? sq : sk) + r * LDV;
        float s0 = 0.f, s1 = 0.f;
#pragma unroll
        for (int c = 0; c < 8; c++) {
            uint4 u = *(const uint4*)(row + c * 8);
            const __half2* hp = (const __half2*)&u;
#pragma unroll
            for (int t2 = 0; t2 < 4; t2++) {
                float2 f = __half22float2(hp[t2]);
                s0 = fmaf(f.x, f.x, s0);
                s1 = fmaf(f.y, f.y, s1);
            }
        }
        float inv = 1.f / fmaxf(sqrtf(s0 + s1), 1e-12f);
        (tid < 64 ? rq : rk)[r] = inv;
    }
    __syncthreads();

    const int r0 = wid * 16;
    const uint32_t qbase = s2u(sq) +
        (uint32_t)(((r0 + (lane & 15)) * LDV + ((lane >> 4) & 1) * 8) * 2);
    const uint32_t kbase = s2u(sk) +
        (uint32_t)((((lane & 7) + ((lane >> 4) << 3)) * LDV + ((lane >> 3) & 1) * 8) * 2);

    // S = q @ k^T  (raw, fp16 MMA, fp32 accum)
    float sacc[8][4];
#pragma unroll
    for (int f = 0; f < 8; f++)
#pragma unroll
        for (int e = 0; e < 4; e++) sacc[f][e] = 0.f;

#pragma unroll
    for (int kg = 0; kg < 4; kg++) {
        uint32_t aq[4];
        LDSM4(aq, qbase + (uint32_t)(kg * 32));
#pragma unroll
        for (int ng = 0; ng < 4; ng++) {
            uint32_t bk[4];
            LDSM4(bk, kbase + (uint32_t)(ng * 16 * LDV * 2 + kg * 32));
            MMAH16816(sacc[ng * 2],     aq, bk[0], bk[1]);
            MMAH16816(sacc[ng * 2 + 1], aq, bk[2], bk[3]);
        }
    }

    // scale by rinv_q * rinv_k * logit_scale, add cpb + mask
    const float sc = expf(fminf(logit_scale[h], 4.605170185988091f));
    const int rlo = r0 + (lane >> 2);
    const int rhi = rlo + 8;
    const float qlo = rq[rlo] * sc;
    const float qhi = rq[rhi] * sc;
    const float* mrow = mask + (size_t)(b & 63) * NTOK * NTOK;
#pragma unroll
    for (int nf = 0; nf < 8; nf++) {
        int c0 = nf * 8 + (lane & 3) * 2;
        float rk0 = rk[c0], rk1 = rk[c0 + 1];
        float2 mlo2 = __ldg((const float2*)(mrow + rlo * 64 + c0));
        float2 mhi2 = __ldg((const float2*)(mrow + rhi * 64 + c0));
        int tlo = ((rlo >> 3) - (c0 >> 3) + 7) * 15 + ((rlo & 7) - (c0 & 7) + 7);
        int thi = tlo + 15;
        sacc[nf][0] = sacc[nf][0] * qlo * rk0 + scpb[tlo] + mlo2.x;
        sacc[nf][1] = sacc[nf][1] * qlo * rk1 + scpb[tlo - 1] + mlo2.y;
        sacc[nf][2] = sacc[nf][2] * qhi * rk0 + scpb[thi] + mhi2.x;
        sacc[nf][3] = sacc[nf][3] * qhi * rk1 + scpb[thi - 1] + mhi2.y;
    }

    // register softmax (rows rlo / rhi, 4-lane groups share a row)
    float mlo = -1e30f, mhi = -1e30f;
#pragma unroll
    for (int nf = 0; nf < 8; nf++) {
        mlo = fmaxf(mlo, fmaxf(sacc[nf][0], sacc[nf][1]));
        mhi = fmaxf(mhi, fmaxf(sacc[nf][2], sacc[nf][3]));
    }
#pragma unroll
    for (int o = 1; o <= 2; o <<= 1) {
        mlo = fmaxf(mlo, __shfl_xor_sync(0xffffffffu, mlo, o));
        mhi = fmaxf(mhi, __shfl_xor_sync(0xffffffffu, mhi, o));
    }
    float slo = 0.f, shi = 0.f;
#pragma unroll
    for (int nf = 0; nf < 8; nf++) {
        sacc[nf][0] = __expf(sacc[nf][0] - mlo); slo += sacc[nf][0];
        sacc[nf][1] = __expf(sacc[nf][1] - mlo); slo += sacc[nf][1];
        sacc[nf][2] = __expf(sacc[nf][2] - mhi); shi += sacc[nf][2];
        sacc[nf][3] = __expf(sacc[nf][3] - mhi); shi += sacc[nf][3];
    }
#pragma unroll
    for (int o = 1; o <= 2; o <<= 1) {
        slo += __shfl_xor_sync(0xffffffffu, slo, o);
        shi += __shfl_xor_sync(0xffffffffu, shi, o);
    }
    const float ilo = 1.f / slo, ihi = 1.f / shi;

    // P c-frags -> fp16 A-frags (pure register repack)
    uint32_t pa[4][4];
#pragma unroll
    for (int g = 0; g < 4; g++) {
        pa[g][0] = h2u(__floats2half2_rn(sacc[2 * g][0] * ilo, sacc[2 * g][1] * ilo));
        pa[g][1] = h2u(__floats2half2_rn(sacc[2 * g][2] * ihi, sacc[2 * g][3] * ihi));
        pa[g][2] = h2u(__floats2half2_rn(sacc[2 * g + 1][0] * ilo, sacc[2 * g + 1][1] * ilo));
        pa[g][3] = h2u(__floats2half2_rn(sacc[2 * g + 1][2] * ihi, sacc[2 * g + 1][3] * ihi));
    }

    // O = P @ V  (V via ldmatrix.trans)
    float oacc[8][4];
#pragma unroll
    for (int f = 0; f < 8; f++)
#pragma unroll
        for (int e = 0; e < 4; e++) oacc[f][e] = 0.f;

    const uint32_t vbase = s2u(sv) +
        (uint32_t)(((lane & 15) * LDV + ((lane >> 4) & 1) * 8) * 2);
#pragma unroll
    for (int kg = 0; kg < 4; kg++) {
#pragma unroll
        for (int ng = 0; ng < 4; ng++) {
            uint32_t bv[4];
            LDSM4T(bv, vbase + (uint32_t)(kg * 16 * LDV * 2 + ng * 32));
            MMAH16816(oacc[ng * 2],     pa[kg], bv[0], bv[1]);
            MMAH16816(oacc[ng * 2 + 1], pa[kg], bv[2], bv[3]);
        }
    }

    // write O as fp16 hi/lo (input to proj GEMM)
#pragma unroll
    for (int nf = 0; nf < 8; nf++) {
        int col = h * HDIM + nf * 8 + (lane & 3) * 2;
        size_t offlo = (size_t)(b * NTOK + rlo) * CDIM + col;
        size_t offhi = (size_t)(b * NTOK + rhi) * CDIM + col;
        float o0 = oacc[nf][0], o1 = oacc[nf][1];
        float o2 = oacc[nf][2], o3 = oacc[nf][3];
        __half a0 = __float2half(o0), a1 = __float2half(o1);
        __half a2 = __float2half(o2), a3 = __float2half(o3);
        *(__half2*)(g_ahi + offlo) = __halves2half2(a0, a1);
        *(__half2*)(g_ahi + offhi) = __halves2half2(a2, a3);
        *(__half2*)(g_alo + offlo) = __halves2half2(
            __float2half(o0 - __half2float(a0)), __float2half(o1 - __half2float(a1)));
        *(__half2*)(g_alo + offhi) = __halves2half2(
            __float2half(o2 - __half2float(a2)), __float2half(o3 - __half2float(a3)));
    }
}

// ---------------------------------------------------------------------------
// launch
// ---------------------------------------------------------------------------
extern "C" void kernel_launch(void* const* d_in, const int* in_sizes, int n_in,
                              void* d_out, int out_size) {
    const float* x           = (const float*)d_in[0];
    const float* mask        = (const float*)d_in[1];
    const float* qkv_w       = (const float*)d_in[2];
    const float* q_bias      = (const float*)d_in[3];
    const float* v_bias      = (const float*)d_in[4];
    const float* logit_scale = (const float*)d_in[5];
    const float* cpb_w1      = (const float*)d_in[6];
    const float* cpb_b1      = (const float*)d_in[7];
    const float* cpb_w2      = (const float*)d_in[8];
    const float* proj_w      = (const float*)d_in[9];
    const float* proj_b      = (const float*)d_in[10];
    float* out = (float*)d_out;

    float* bias_p;
    __half *qkvh, *xhi, *xlo, *wh, *ph, *ahi, *alo;
    cudaGetSymbolAddress((void**)&qkvh, g_qkvh);
    cudaGetSymbolAddress((void**)&bias_p, g_bias);
    cudaGetSymbolAddress((void**)&xhi, g_xhi);
    cudaGetSymbolAddress((void**)&xlo, g_xlo);
    cudaGetSymbolAddress((void**)&wh, g_wh);
    cudaGetSymbolAddress((void**)&ph, g_ph);
    cudaGetSymbolAddress((void**)&ahi, g_ahi);
    cudaGetSymbolAddress((void**)&alo, g_alo);

    cudaFuncSetAttribute(gemm2h<true>,  cudaFuncAttributeMaxDynamicSharedMemorySize, GEMM_SMEM);
    cudaFuncSetAttribute(gemm2h<false>, cudaFuncAttributeMaxDynamicSharedMemorySize, GEMM_SMEM);
    cudaFuncSetAttribute(attn_mma, cudaFuncAttributeMaxDynamicSharedMemorySize, ATTN_SMEM);

    // conversions + tables
    conv_hilo_h<<<8192, 256>>>((const float4*)x, xhi, xlo, MTOT * CDIM / 4);
    conv_h2<<<1024, 256>>>((const float4*)qkv_w, wh, QKVN * CDIM / 4,
                           (const float4*)proj_w, ph, CDIM * CDIM / 4);
    cpb_bias_kernel<<<249, 64>>>(cpb_w1, cpb_b1, cpb_w2, q_bias, v_bias);

    // QKV projection -> fp16 qkv: grid (12, 512)
    {
        dim3 grid(QKVN / 128, MTOT / 128);
        gemm2h<true><<<grid, 256, GEMM_SMEM>>>(xhi, xlo, wh, nullptr, qkvh, bias_p, QKVN);
    }

    // fused HMMA attention
    {
        dim3 grid(BATCH, NHEAD);
        attn_mma<<<grid, 128, ATTN_SMEM>>>(mask, logit_scale);
    }

    // output projection -> d_out fp32: grid (4, 512)
    {
        dim3 grid(CDIM / 128, MTOT / 128);
        gemm2h<false><<<grid, 256, GEMM_SMEM>>>(ahi, alo, ph, out, nullptr, proj_b, CDIM);
    }
}